// round 11
// baseline (speedup 1.0000x reference)
#include <cuda_runtime.h>
#include <math.h>
#include <stdint.h>

#define Bn 4
#define Tn 8192
#define Dn 1024
#define Hn 8
#define HDn 128
#define Cn 64
#define Nchunk 128
#define BTn (Bn*Tn)
#define BHn (Bn*Hn)

// ---------------- scratch (device globals; no cudaMalloc allowed) ----------
__device__ float g_v[(size_t)BTn*Dn];       // v*beta -> v' (in place)
__device__ float g_rk[(size_t)BTn*Dn];      // normalized read keys, (B,H,T,d)
__device__ float g_wkcd[(size_t)BTn*Dn];    // wk_cumdecay, (B,H,T,d)
__device__ float g_o[(size_t)BTn*Dn];       // gated per-head output, (B,T,D)
__device__ float g_attn[(size_t)BHn*Nchunk*Cn*Cn];
__device__ float g_beta[BHn*Tn];            // (B,H,T)
__device__ float g_gate[BHn*Tn];
__device__ float g_dec[BHn*Tn];             // decay, then in-chunk cumsum (in place)

__device__ __forceinline__ float warp_sum(float v) {
#pragma unroll
  for (int o = 16; o > 0; o >>= 1) v += __shfl_xor_sync(0xffffffffu, v, o);
  return v;
}

// ======================= mma.sync tf32 helpers ==============================
__device__ __forceinline__ uint32_t smem_u32(const void* p) {
  uint32_t a;
  asm("{ .reg .u64 t; cvta.to.shared.u64 t, %1; cvt.u32.u64 %0, t; }"
      : "=r"(a) : "l"(p));
  return a;
}

__device__ __forceinline__ uint32_t tf32u(float a) {
  uint32_t r; asm("cvt.rna.tf32.f32 %0, %1;" : "=r"(r) : "f"(a)); return r;
}

__device__ __forceinline__ void split2(float x, uint32_t& hi, uint32_t& lo) {
  hi = tf32u(x);
  lo = tf32u(x - __uint_as_float(hi));
}

__device__ __forceinline__ void mma_tf32(float* c, const uint32_t* a,
                                         const uint32_t* b) {
  asm volatile(
      "mma.sync.aligned.m16n8k8.row.col.f32.tf32.tf32.f32 "
      "{%0,%1,%2,%3}, {%4,%5,%6,%7}, {%8,%9}, {%0,%1,%2,%3};"
      : "+f"(c[0]), "+f"(c[1]), "+f"(c[2]), "+f"(c[3])
      : "r"(a[0]), "r"(a[1]), "r"(a[2]), "r"(a[3]), "r"(b[0]), "r"(b[1]));
}

__device__ __forceinline__ void cp16(uint32_t dst, const void* src) {
  asm volatile("cp.async.cg.shared.global [%0], [%1], 16;"
               :: "r"(dst), "l"(src) : "memory");
}
#define CP_COMMIT() asm volatile("cp.async.commit_group;" ::: "memory")
#define CP_WAIT0() asm volatile("cp.async.wait_group 0;" ::: "memory")

// ---------------- 1) per-token projections + rk normalize ------------------
__global__ __launch_bounds__(256) void k_proj_small(
    const float* __restrict__ x, const float* __restrict__ Wg,
    const float* __restrict__ Wb, const float* __restrict__ Wa,
    const float* __restrict__ dtb, const float* __restrict__ Alog) {
  __shared__ float xs[Dn];
  int row = blockIdx.x;                  // b*T + t
  const float* xr = x + (size_t)row * Dn;
  for (int i = threadIdx.x; i < Dn; i += 256) xs[i] = xr[i];
  __syncthreads();
  int h = threadIdx.x >> 5, lane = threadIdx.x & 31;
  const float* wg = Wg + h * Dn;
  const float* wb = Wb + h * Dn;
  const float* wa = Wa + h * Dn;
  float sg = 0.f, sb = 0.f, sa = 0.f;
  for (int i = lane; i < Dn; i += 32) {
    float xv = xs[i];
    sg += xv * wg[i]; sb += xv * wb[i]; sa += xv * wa[i];
  }
  sg = warp_sum(sg); sb = warp_sum(sb); sa = warp_sum(sa);
  float ss = 0.f;
  for (int i = lane; i < HDn; i += 32) { float v = xs[h*HDn + i]; ss += v*v; }
  ss = warp_sum(ss);
  float inv = 1.0f / fmaxf(sqrtf(ss), 1e-12f);
  int b = row >> 13, t = row & (Tn - 1);
  size_t bh = (size_t)b * Hn + h;
  float* rko = g_rk + (bh * Tn + t) * HDn;
  for (int i = lane; i < HDn; i += 32) rko[i] = xs[h*HDn + i] * inv;
  if (lane == 0) {
    g_gate[bh*Tn + t] = 1.0f / (1.0f + expf(-sg));
    g_beta[bh*Tn + t] = 1.0f / (1.0f + expf(-sb));
    float z = sa + dtb[h];
    float sp = (z > 20.0f) ? z : log1pf(expf(z));
    g_dec[bh*Tn + t] = -expf(Alog[h]) * sp;
  }
}

// ---------------- 2) in-chunk cumsum of decay ------------------------------
__global__ void k_cumsum() {
  int idx = blockIdx.x;                  // bh*N + n
  int bh = idx >> 7, n = idx & (Nchunk - 1);
  size_t base = (size_t)bh * Tn + (size_t)n * Cn;
  float v = g_dec[base + threadIdx.x];
  int lane = threadIdx.x & 31, w = threadIdx.x >> 5;
#pragma unroll
  for (int o = 1; o < 32; o <<= 1) {
    float u = __shfl_up_sync(0xffffffffu, v, o);
    if (lane >= o) v += u;
  }
  __shared__ float tot;
  if (w == 0 && lane == 31) tot = v;
  __syncthreads();
  if (w == 1) v += tot;
  g_dec[base + threadIdx.x] = v;
}

// ---------------- 3/6) mma.sync tf32 GEMM, pre-split hi/lo staging ---------
#define KCH 32                            // K per chunk
#define ASTRIDE 36                        // padded floats per row
#define PART_F (128*ASTRIDE)              // one hi or lo plane
#define GM_SMEM (4*PART_F*4)              // Ahi, Alo, Bhi, Blo

__global__ __launch_bounds__(256) void k_mma(
    const float* __restrict__ Ain, const float* __restrict__ Bw,
    const float* __restrict__ X, float* __restrict__ Out, int mode) {
  extern __shared__ float sf[];
  float* Ahi = sf;
  float* Alo = Ahi + PART_F;
  float* Bhi = Alo + PART_F;
  float* Blo = Bhi + PART_F;
  int tid = threadIdx.x, wid = tid >> 5, lane = tid & 31;
  int n0 = blockIdx.x * 128;
  int m0 = blockIdx.y * 128;
  int wm = wid >> 2, wn = wid & 3;       // warp tile: rows wm*64, cols wn*32
  int g = lane >> 2, t = lane & 3;

  // device-side resolution of the device-global operand (ATS trap otherwise)
  const float* A = (mode == 0) ? Ain : (const float*)g_o;

  float acc[4][4][4];
#pragma unroll
  for (int mi = 0; mi < 4; mi++)
#pragma unroll
    for (int ni = 0; ni < 4; ni++)
#pragma unroll
      for (int r = 0; r < 4; r++) acc[mi][ni][r] = 0.0f;

  int lrow = tid >> 3, lc4 = tid & 7;    // per-q: row = lrow + 32q, cols lc4*4..
  float4 pa[4], pb[4];

  auto ldg = [&](int kc) {
#pragma unroll
    for (int q = 0; q < 4; q++) {
      int row = lrow + 32 * q;
      pa[q] = *(const float4*)(A  + (size_t)(m0 + row) * Dn + kc * KCH + lc4 * 4);
      pb[q] = *(const float4*)(Bw + (size_t)(n0 + row) * Dn + kc * KCH + lc4 * 4);
    }
  };
  auto stage = [&]() {
#pragma unroll
    for (int q = 0; q < 4; q++) {
      int row = lrow + 32 * q;
      int off = row * ASTRIDE + lc4 * 4;
      uint32_t h0, l0, h1, l1, h2, l2, h3, l3;
      split2(pa[q].x, h0, l0); split2(pa[q].y, h1, l1);
      split2(pa[q].z, h2, l2); split2(pa[q].w, h3, l3);
      *(float4*)(Ahi + off) = make_float4(__uint_as_float(h0), __uint_as_float(h1),
                                          __uint_as_float(h2), __uint_as_float(h3));
      *(float4*)(Alo + off) = make_float4(__uint_as_float(l0), __uint_as_float(l1),
                                          __uint_as_float(l2), __uint_as_float(l3));
      split2(pb[q].x, h0, l0); split2(pb[q].y, h1, l1);
      split2(pb[q].z, h2, l2); split2(pb[q].w, h3, l3);
      *(float4*)(Bhi + off) = make_float4(__uint_as_float(h0), __uint_as_float(h1),
                                          __uint_as_float(h2), __uint_as_float(h3));
      *(float4*)(Blo + off) = make_float4(__uint_as_float(l0), __uint_as_float(l1),
                                          __uint_as_float(l2), __uint_as_float(l3));
    }
  };

  const int NC = Dn / KCH;               // 32 chunks
  ldg(0);
  for (int kc = 0; kc < NC; kc++) {
    stage();
    if (kc + 1 < NC) ldg(kc + 1);        // prefetch next chunk into registers
    __syncthreads();                     // stage visible to all
#pragma unroll
    for (int kk = 0; kk < 4; kk++) {
      uint32_t ah[4][4], al[4][4];
#pragma unroll
      for (int mi = 0; mi < 4; mi++) {
        int r0 = wm * 64 + mi * 16 + g;
        int o00 = r0 * ASTRIDE + kk * 8 + t;
        int o10 = (r0 + 8) * ASTRIDE + kk * 8 + t;
        ah[mi][0] = __float_as_uint(Ahi[o00]);
        ah[mi][1] = __float_as_uint(Ahi[o10]);
        ah[mi][2] = __float_as_uint(Ahi[o00 + 4]);
        ah[mi][3] = __float_as_uint(Ahi[o10 + 4]);
        al[mi][0] = __float_as_uint(Alo[o00]);
        al[mi][1] = __float_as_uint(Alo[o10]);
        al[mi][2] = __float_as_uint(Alo[o00 + 4]);
        al[mi][3] = __float_as_uint(Alo[o10 + 4]);
      }
      uint32_t bh[4][2], bl[4][2];
#pragma unroll
      for (int ni = 0; ni < 4; ni++) {
        int r0 = wn * 32 + ni * 8 + g;
        int o0 = r0 * ASTRIDE + kk * 8 + t;
        bh[ni][0] = __float_as_uint(Bhi[o0]);
        bh[ni][1] = __float_as_uint(Bhi[o0 + 4]);
        bl[ni][0] = __float_as_uint(Blo[o0]);
        bl[ni][1] = __float_as_uint(Blo[o0 + 4]);
      }
#pragma unroll
      for (int mi = 0; mi < 4; mi++)
#pragma unroll
        for (int ni = 0; ni < 4; ni++) {
          mma_tf32(acc[mi][ni], ah[mi], bh[ni]);
          mma_tf32(acc[mi][ni], ah[mi], bl[ni]);
          mma_tf32(acc[mi][ni], al[mi], bh[ni]);
        }
    }
    __syncthreads();                     // MMA done before stage overwrite
  }

  int h = blockIdx.x;                     // mode 0: 128-wide n-block == head
#pragma unroll
  for (int mi = 0; mi < 4; mi++) {
#pragma unroll
    for (int rr = 0; rr < 2; rr++) {
      int m = m0 + wm * 64 + mi * 16 + g + rr * 8;
      if (mode == 0) {
        int b = m >> 13, tt = m & (Tn - 1);
        size_t bhT = ((size_t)(b * Hn + h)) * Tn + tt;
        float beta = g_beta[bhT];
        float* vout = g_v + bhT * HDn;
#pragma unroll
        for (int ni = 0; ni < 4; ni++) {
          int col = wn * 32 + ni * 8 + 2 * t;
          float2 val;
          val.x = acc[mi][ni][rr * 2 + 0] * beta;
          val.y = acc[mi][ni][rr * 2 + 1] * beta;
          *(float2*)(vout + col) = val;
        }
      } else {
#pragma unroll
        for (int ni = 0; ni < 4; ni++) {
          int ncol = n0 + wn * 32 + ni * 8 + 2 * t;
          size_t off = (size_t)m * Dn + ncol;
          float2 xv = *(const float2*)(X + off);
          float2 val;
          val.x = xv.x + acc[mi][ni][rr * 2 + 0];
          val.y = xv.y + acc[mi][ni][rr * 2 + 1];
          *(float2*)(Out + off) = val;
        }
      }
    }
  }
}

// ---------------- 4) per-chunk: P (mma), M, (I+M)^-1, wkcd/v' (mma) --------
#define RS 132
#define K4_SMEM ((65*RS + 2*64*65 + 4*64) * 4)
__global__ __launch_bounds__(256) void k_chunk() {
  extern __shared__ float smf[];
  float* rbuf  = smf;                    // 65 x 132: row0 = wk0, rows1..64 = rk; later v
  float* Msm   = rbuf + 65*RS;           // 64 x 65
  float* Asm   = Msm + 64*65;            // 64 x 65 (P' lower, then inverse)
  float* decS  = Asm + 64*65;            // 64
  float* betaS = decS + 64;
  float* facS  = betaS + 64;             // beta_i * exp(dec_i - dec_{i-1})
  float* beS   = facS + 64;

  int cid = blockIdx.x;                  // bh*N + n
  int bh = cid >> 7, n = cid & (Nchunk - 1);
  int tid = threadIdx.x;
  int wid = tid >> 5, lane = tid & 31;
  int g = lane >> 2, t = lane & 3;
  size_t tbase = (size_t)bh * Tn + (size_t)n * Cn;
  const float* rkG = g_rk + tbase * HDn;

  for (int i = tid; i < 64*128; i += 256) {
    int c = i >> 7, d = i & 127;
    rbuf[(c+1)*RS + d] = rkG[(size_t)c*HDn + d];
  }
  if (tid < 128) rbuf[tid] = (n == 0) ? 0.0f : g_rk[(tbase - 1) * HDn + tid];
  if (tid >= 128 && tid < 192) {
    int c = tid - 128;
    float dv = g_dec[tbase + c];
    float bv = g_beta[tbase + c];
    decS[c] = dv; betaS[c] = bv; beS[c] = bv * __expf(dv);
  }
  __syncthreads();
  if (tid < 64) facS[tid] = (tid == 0) ? 0.0f
                          : betaS[tid] * __expf(decS[tid] - decS[tid-1]);

  // ---- P[i][j] = rk_i . wk_j via mma (3xTF32); wk_j = rbuf row j ----------
  int wr = wid >> 2, wc = wid & 3;       // 2 x 4 warp grid over 64x64
  float pacc[2][2][4];
#pragma unroll
  for (int mi = 0; mi < 2; mi++)
#pragma unroll
    for (int ni = 0; ni < 2; ni++)
#pragma unroll
      for (int r = 0; r < 4; r++) pacc[mi][ni][r] = 0.0f;

#pragma unroll 2
  for (int ks = 0; ks < 16; ks++) {
    int col = ks*8 + t;
    uint32_t ah[2][4], al[2][4];
#pragma unroll
    for (int mi = 0; mi < 2; mi++) {
      int r0 = 1 + wr*32 + mi*16 + g;
      split2(rbuf[r0*RS + col],         ah[mi][0], al[mi][0]);
      split2(rbuf[(r0+8)*RS + col],     ah[mi][1], al[mi][1]);
      split2(rbuf[r0*RS + col + 4],     ah[mi][2], al[mi][2]);
      split2(rbuf[(r0+8)*RS + col + 4], ah[mi][3], al[mi][3]);
    }
    uint32_t bhf[2][2], blf[2][2];
#pragma unroll
    for (int ni = 0; ni < 2; ni++) {
      int nr = wc*16 + ni*8 + g;
      split2(rbuf[nr*RS + col],     bhf[ni][0], blf[ni][0]);
      split2(rbuf[nr*RS + col + 4], bhf[ni][1], blf[ni][1]);
    }
#pragma unroll
    for (int mi = 0; mi < 2; mi++)
#pragma unroll
      for (int ni = 0; ni < 2; ni++) {
        mma_tf32(pacc[mi][ni], ah[mi], bhf[ni]);
        mma_tf32(pacc[mi][ni], ah[mi], blf[ni]);
        mma_tf32(pacc[mi][ni], al[mi], bhf[ni]);
      }
  }

  // epilogue: attn = P * exp(dec_i - dec_j) masked; also P' lower into Asm
  float* attnOut = g_attn + (size_t)cid * 4096;
#pragma unroll
  for (int mi = 0; mi < 2; mi++)
#pragma unroll
    for (int ni = 0; ni < 2; ni++)
#pragma unroll
      for (int r = 0; r < 4; r++) {
        int i = wr*32 + mi*16 + g + ((r & 2) ? 8 : 0);
        int j = wc*16 + ni*8 + 2*t + (r & 1);
        float aval = 0.0f;
        if (i >= j) {
          aval = pacc[mi][ni][r] * __expf(decS[i] - decS[j]);
          Asm[i*65 + j] = aval;
        }
        attnOut[i*64 + j] = aval;
      }
  __syncthreads();

  // M[i][j] (strict lower) = P'[i-1][j] * beta_i * exp(dec_i - dec_{i-1})
  for (int idx = tid; idx < 4096; idx += 256) {
    int i = idx >> 6, j = idx & 63;
    if (i > j) Msm[i*65 + j] = Asm[(i-1)*65 + j] * facS[i];
  }
  __syncthreads();

  // A := I (also zeros the upper triangle for the dense mma below)
  for (int idx = tid; idx < 4096; idx += 256) {
    int i = idx >> 6, j = idx & 63;
    Asm[i*65 + j] = (i == j) ? 1.0f : 0.0f;
  }
  __syncthreads();

  // forward elimination: A = (I+M)^-1 (unit lower triangular)
  for (int i = 0; i < 63; i++) {
    int ncols = i + 1;
    int tot = (63 - i) * ncols;
    for (int idx = tid; idx < tot; idx += 256) {
      int q = idx / ncols;
      int ip = i + 1 + q;
      int k = idx - q * ncols;
      Asm[ip*65 + k] -= Msm[ip*65 + i] * Asm[i*65 + k];
    }
    __syncthreads();
  }

  // scale wk rows in place: rbuf row j *= beta_j * exp(dec_j)
  for (int i = tid; i < 64*128; i += 256) {
    int j = i >> 7, d = i & 127;
    rbuf[j*RS + d] *= beS[j];
  }
  __syncthreads();

  // C = Asm @ Xs (64x128, K=64), 3xTF32 mma; Xs rows in rbuf (stride RS)
  int wr2 = wid >> 1, wc2 = wid & 1;
  auto triMul = [&](float* outp) {
    float cacc[8][4];
#pragma unroll
    for (int ni = 0; ni < 8; ni++)
#pragma unroll
      for (int r = 0; r < 4; r++) cacc[ni][r] = 0.0f;
#pragma unroll 1
    for (int ks = 0; ks < 8; ks++) {
      int col = ks*8 + t;
      uint32_t ah4[4], al4[4];
      int r0 = wr2*16 + g;
      split2(Asm[r0*65 + col],       ah4[0], al4[0]);
      split2(Asm[(r0+8)*65 + col],   ah4[1], al4[1]);
      split2(Asm[r0*65 + col+4],     ah4[2], al4[2]);
      split2(Asm[(r0+8)*65 + col+4], ah4[3], al4[3]);
#pragma unroll
      for (int ni = 0; ni < 8; ni++) {
        int nn = wc2*64 + ni*8 + g;
        uint32_t bh2[2], bl2[2];
        split2(rbuf[col*RS + nn],       bh2[0], bl2[0]);
        split2(rbuf[(col+4)*RS + nn],   bh2[1], bl2[1]);
        mma_tf32(cacc[ni], ah4, bh2);
        mma_tf32(cacc[ni], ah4, bl2);
        mma_tf32(cacc[ni], al4, bh2);
      }
    }
#pragma unroll
    for (int ni = 0; ni < 8; ni++)
#pragma unroll
      for (int rr = 0; rr < 2; rr++) {
        int c = wr2*16 + g + rr*8;
        int d = wc2*64 + ni*8 + 2*t;
        float2 val;
        val.x = cacc[ni][rr*2 + 0];
        val.y = cacc[ni][rr*2 + 1];
        *(float2*)(outp + (size_t)c*HDn + d) = val;
      }
  };

  // wkcd = A^-1 @ (wk * beta * exp(dec))
  triMul(g_wkcd + tbase * HDn);
  __syncthreads();

  // load v (already *beta) into rbuf rows 0..63
  {
    const float* vG = g_v + tbase * HDn;
    for (int i = tid; i < 64*128; i += 256) {
      int c = i >> 7, d = i & 127;
      rbuf[c*RS + d] = vG[(size_t)c*HDn + d];
    }
  }
  __syncthreads();

  // v' = A^-1 @ v
  triMul(g_v + tbase * HDn);
}

// ---------------- 5) inter-chunk recurrence, tensorized --------------------
// S layouts: d-major, stride 40 (B-operand conflict-free: 8*40 % 32 == 8)
#define SS 40
#define ATS 68
#define K5_SMEM ((3*128*SS + 4*64*SS + 64*ATS + 64*RS + 65*RS + 2*64) * 4)
__global__ __launch_bounds__(256) void k_recur() {
  extern __shared__ float smf[];
  float* S      = smf;                   // 128 x 40 fp32
  float* S_hi   = S     + 128*SS;        // tf32 hi copy
  float* S_lo   = S_hi  + 128*SS;        // tf32 lo copy
  float* vn_hi  = S_lo  + 128*SS;        // 64 x 40
  float* vn_lo  = vn_hi + 64*SS;
  float* vns_hi = vn_lo + 64*SS;         // edw-scaled vn
  float* vns_lo = vns_hi+ 64*SS;
  float* attnS  = vns_lo+ 64*SS;         // 64 x 68
  float* bufA   = attnS + 64*ATS;        // 64 x 132 (wkcd)
  float* bufB   = bufA  + 64*RS;         // 65 x 132 (row0=wk0, 1..64=rk)
  float* edwS   = bufB  + 65*RS;         // 64
  float* edcS   = edwS  + 64;            // 64

  uint32_t smb = smem_u32(smf);
  int blk = blockIdx.x;                  // bh*4 + eg
  int bh = blk >> 2, eg = blk & 3;
  int e0 = eg * 32;
  int b = bh >> 3, h = bh & 7;
  int tid = threadIdx.x;
  int wid = tid >> 5, lane = tid & 31;
  int g = lane >> 2, t = lane & 3;

  for (int i = tid; i < 3*128*SS; i += 256) S[i] = 0.0f;
  __syncthreads();

  uint32_t sm_attn = smb + (uint32_t)((attnS - smf) * 4);
  uint32_t sm_bufA = smb + (uint32_t)((bufA - smf) * 4);
  uint32_t sm_bufB = smb + (uint32_t)((bufB - smf) * 4);

  for (int n = 0; n < Nchunk; n++) {
    size_t tbase = (size_t)bh * Tn + (size_t)n * Cn;
    // ---- loads (cp.async) ----
    {
      const float* aG = g_attn + ((size_t)bh * Nchunk + n) * 4096;
#pragma unroll
      for (int q = 0; q < 4; q++) {
        int idx = q * 256 + tid;
        int r = idx >> 4, c4 = idx & 15;
        cp16(sm_attn + (uint32_t)(r * ATS + c4 * 4) * 4, aG + r * 64 + c4 * 4);
      }
      const float* wkcdG = g_wkcd + tbase * HDn;
      const float* rkG = g_rk + tbase * HDn;
#pragma unroll
      for (int q = 0; q < 8; q++) {
        int idx = q * 256 + tid;
        int r = idx >> 5, c4 = idx & 31;
        cp16(sm_bufA + (uint32_t)(r * RS + c4 * 4) * 4,
             wkcdG + (size_t)r * HDn + c4 * 4);
        cp16(sm_bufB + (uint32_t)((r + 1) * RS + c4 * 4) * 4,
             rkG + (size_t)r * HDn + c4 * 4);
      }
      if (tid < 32) {
        if (n == 0) {
          float4 z = make_float4(0.f, 0.f, 0.f, 0.f);
          *(float4*)(bufB + tid * 4) = z;
        } else {
          cp16(sm_bufB + (uint32_t)(tid * 4) * 4,
               g_rk + (tbase - 1) * HDn + tid * 4);
        }
      }
      if (tid < 64) {
        float dv = g_dec[tbase + tid];
        float d63 = g_dec[tbase + 63];
        edcS[tid] = __expf(dv);
        edwS[tid] = __expf(d63 - dv);
      }
      CP_COMMIT(); CP_WAIT0();
    }
    __syncthreads();   // sync 1: tiles + S (from prev chunk) visible

    // ---- phase A: warps 0-3 vnew = v' - wkcd@S ; warps 4-7 oS = rk@S -----
    float acc[4][4];
    int w4 = wid & 3;
    int m0 = w4 * 16;
    bool isV = (wid < 4);
    if (isV) {
      const float* vG = g_v + tbase * HDn;
#pragma unroll
      for (int ni = 0; ni < 4; ni++) {
        int e = ni * 8 + 2 * t;
        float2 p0 = *(const float2*)(vG + (size_t)(m0 + g) * HDn + e0 + e);
        float2 p1 = *(const float2*)(vG + (size_t)(m0 + 8 + g) * HDn + e0 + e);
        acc[ni][0] = p0.x; acc[ni][1] = p0.y;
        acc[ni][2] = p1.x; acc[ni][3] = p1.y;
      }
    } else {
#pragma unroll
      for (int ni = 0; ni < 4; ni++)
#pragma unroll
        for (int r = 0; r < 4; r++) acc[ni][r] = 0.0f;
    }
    {
      const float* Abuf = isV ? bufA : (bufB + RS);  // rk rows offset by 1
      float sgn = isV ? -1.0f : 1.0f;
#pragma unroll 2
      for (int ks = 0; ks < 16; ks++) {
        int k0 = ks * 8;
        uint32_t ah[4], al[4];
        split2(sgn * Abuf[(m0 + g) * RS + k0 + t],         ah[0], al[0]);
        split2(sgn * Abuf[(m0 + 8 + g) * RS + k0 + t],     ah[1], al[1]);
        split2(sgn * Abuf[(m0 + g) * RS + k0 + t + 4],     ah[2], al[2]);
        split2(sgn * Abuf[(m0 + 8 + g) * RS + k0 + t + 4], ah[3], al[3]);
#pragma unroll
        for (int ni = 0; ni < 4; ni++) {
          int nn = ni * 8 + g;
          uint32_t bh2[2], bl2[2];
          bh2[0] = __float_as_uint(S_hi[(k0 + t) * SS + nn]);
          bh2[1] = __float_as_uint(S_hi[(k0 + t + 4) * SS + nn]);
          bl2[0] = __float_as_uint(S_lo[(k0 + t) * SS + nn]);
          bl2[1] = __float_as_uint(S_lo[(k0 + t + 4) * SS + nn]);
          mma_tf32(acc[ni], ah, bh2);
          mma_tf32(acc[ni], ah, bl2);
          mma_tf32(acc[ni], al, bh2);
        }
      }
    }
    if (isV) {
#pragma unroll
      for (int ni = 0; ni < 4; ni++)
#pragma unroll
        for (int r = 0; r < 4; r++) {
          int c = m0 + g + ((r & 2) ? 8 : 0);
          int e = ni * 8 + 2 * t + (r & 1);
          float v = acc[ni][r];
          uint32_t hh, ll;
          split2(v, hh, ll);
          vn_hi[c * SS + e] = __uint_as_float(hh);
          vn_lo[c * SS + e] = __uint_as_float(ll);
          float vs = v * edwS[c];
          split2(vs, hh, ll);
          vns_hi[c * SS + e] = __uint_as_float(hh);
          vns_lo[c * SS + e] = __uint_as_float(ll);
        }
    } else {
#pragma unroll
      for (int ni = 0; ni < 4; ni++) {
        acc[ni][0] *= edcS[m0 + g];     acc[ni][1] *= edcS[m0 + g];
        acc[ni][2] *= edcS[m0 + 8 + g]; acc[ni][3] *= edcS[m0 + 8 + g];
      }
    }
    __syncthreads();   // sync 2: vn arrays visible

    if (!isV) {
      // ---- phase B (warps 4-7): o = oS_scaled + attn @ vn; gated store ----
#pragma unroll 1
      for (int ks = 0; ks < 8; ks++) {
        int k0 = ks * 8;
        uint32_t ah[4], al[4];
        split2(attnS[(m0 + g) * ATS + k0 + t],         ah[0], al[0]);
        split2(attnS[(m0 + 8 + g) * ATS + k0 + t],     ah[1], al[1]);
        split2(attnS[(m0 + g) * ATS + k0 + t + 4],     ah[2], al[2]);
        split2(attnS[(m0 + 8 + g) * ATS + k0 + t + 4], ah[3], al[3]);
#pragma unroll
        for (int ni = 0; ni < 4; ni++) {
          int nn = ni * 8 + g;
          uint32_t bh2[2], bl2[2];
          bh2[0] = __float_as_uint(vn_hi[(k0 + t) * SS + nn]);
          bh2[1] = __float_as_uint(vn_hi[(k0 + t + 4) * SS + nn]);
          bl2[0] = __float_as_uint(vn_lo[(k0 + t) * SS + nn]);
          bl2[1] = __float_as_uint(vn_lo[(k0 + t + 4) * SS + nn]);
          mma_tf32(acc[ni], ah, bh2);
          mma_tf32(acc[ni], ah, bl2);
          mma_tf32(acc[ni], al, bh2);
        }
      }
#pragma unroll
      for (int rr = 0; rr < 2; rr++) {
        int c = m0 + g + rr * 8;
        int tg = n * Cn + c;
        float gate = g_gate[(size_t)bh * Tn + tg];
        float* op = g_o + ((size_t)b * Tn + tg) * Dn + h * HDn + e0;
#pragma unroll
        for (int ni = 0; ni < 4; ni++) {
          float2 val;
          val.x = acc[ni][rr * 2 + 0] * gate;
          val.y = acc[ni][rr * 2 + 1] * gate;
          *(float2*)(op + ni * 8 + 2 * t) = val;
        }
      }
    } else {
      // ---- update (warps 0-3): S = gl*S + wk^T @ vns -----------------------
      int m0u = w4 * 32;
      float acc2[2][4][4];
#pragma unroll
      for (int mi = 0; mi < 2; mi++)
#pragma unroll
        for (int ni = 0; ni < 4; ni++)
#pragma unroll
          for (int r = 0; r < 4; r++) acc2[mi][ni][r] = 0.0f;
#pragma unroll 1
      for (int ks = 0; ks < 8; ks++) {
        int k0 = ks * 8;
        uint32_t ah[2][4], al[2][4];
#pragma unroll
        for (int mi = 0; mi < 2; mi++) {
          int mm = m0u + mi * 16 + g;
          split2(bufB[(k0 + t) * RS + mm],         ah[mi][0], al[mi][0]);
          split2(bufB[(k0 + t) * RS + mm + 8],     ah[mi][1], al[mi][1]);
          split2(bufB[(k0 + t + 4) * RS + mm],     ah[mi][2], al[mi][2]);
          split2(bufB[(k0 + t + 4) * RS + mm + 8], ah[mi][3], al[mi][3]);
        }
#pragma unroll
        for (int ni = 0; ni < 4; ni++) {
          int nn = ni * 8 + g;
          uint32_t bh2[2], bl2[2];
          bh2[0] = __float_as_uint(vns_hi[(k0 + t) * SS + nn]);
          bh2[1] = __float_as_uint(vns_hi[(k0 + t + 4) * SS + nn]);
          bl2[0] = __float_as_uint(vns_lo[(k0 + t) * SS + nn]);
          bl2[1] = __float_as_uint(vns_lo[(k0 + t + 4) * SS + nn]);
#pragma unroll
          for (int mi = 0; mi < 2; mi++) {
            mma_tf32(acc2[mi][ni], ah[mi], bh2);
            mma_tf32(acc2[mi][ni], ah[mi], bl2);
            mma_tf32(acc2[mi][ni], al[mi], bh2);
          }
        }
      }
      float gl = edcS[63];
#pragma unroll
      for (int mi = 0; mi < 2; mi++)
#pragma unroll
        for (int ni = 0; ni < 4; ni++)
#pragma unroll
          for (int r = 0; r < 4; r++) {
            int d = m0u + mi * 16 + g + ((r & 2) ? 8 : 0);
            int e = ni * 8 + 2 * t + (r & 1);
            float sNew = gl * S[d * SS + e] + acc2[mi][ni][r];
            S[d * SS + e] = sNew;
            uint32_t hh, ll;
            split2(sNew, hh, ll);
            S_hi[d * SS + e] = __uint_as_float(hh);
            S_lo[d * SS + e] = __uint_as_float(ll);
          }
    }
    __syncthreads();   // sync 3: S updated; attn/bufs free for next loads
  }
}

// ---------------------------------------------------------------------------
extern "C" void kernel_launch(void* const* d_in, const int* in_sizes, int n_in,
                              void* d_out, int out_size) {
  (void)in_sizes; (void)n_in; (void)out_size;
  const float* x    = (const float*)d_in[0];
  const float* Ww   = (const float*)d_in[1];
  const float* Wg   = (const float*)d_in[2];
  const float* Wo   = (const float*)d_in[3];
  const float* Wb   = (const float*)d_in[4];
  const float* Wa   = (const float*)d_in[5];
  const float* dtb  = (const float*)d_in[6];
  const float* Alog = (const float*)d_in[7];
  float* out = (float*)d_out;

  cudaFuncSetAttribute(k_mma, cudaFuncAttributeMaxDynamicSharedMemorySize, GM_SMEM);
  cudaFuncSetAttribute(k_chunk, cudaFuncAttributeMaxDynamicSharedMemorySize, K4_SMEM);
  cudaFuncSetAttribute(k_recur, cudaFuncAttributeMaxDynamicSharedMemorySize, K5_SMEM);

  k_proj_small<<<BTn, 256>>>(x, Wg, Wb, Wa, dtb, Alog);
  k_cumsum<<<BHn * Nchunk, 64>>>();
  k_mma<<<dim3(Dn/128, BTn/128), 256, GM_SMEM>>>(x, Ww, x, nullptr, 0);
  k_chunk<<<BHn * Nchunk, 256, K4_SMEM>>>();
  k_recur<<<BHn * 4, 256, K5_SMEM>>>();
  k_mma<<<dim3(Dn/128, BTn/128), 256, GM_SMEM>>>(nullptr, Wo, x, out, 1);
}

// round 12
// speedup vs baseline: 1.3334x; 1.3334x over previous
#include <cuda_runtime.h>
#include <math.h>
#include <stdint.h>

#define Bn 4
#define Tn 8192
#define Dn 1024
#define Hn 8
#define HDn 128
#define Cn 64
#define Nchunk 128
#define BTn (Bn*Tn)
#define BHn (Bn*Hn)

// ---------------- scratch (device globals; no cudaMalloc allowed) ----------
__device__ float g_v[(size_t)BTn*Dn];       // v*beta -> v' (in place)
__device__ float g_rk[(size_t)BTn*Dn];      // normalized read keys, (B,H,T,d)
__device__ float g_wkcd[(size_t)BTn*Dn];    // wk_cumdecay, (B,H,T,d)
__device__ float g_o[(size_t)BTn*Dn];       // gated per-head output, (B,T,D)
__device__ float g_attn[(size_t)BHn*Nchunk*Cn*Cn];
__device__ float g_beta[BHn*Tn];            // (B,H,T)
__device__ float g_gate[BHn*Tn];
__device__ float g_dec[BHn*Tn];             // decay, then in-chunk cumsum (in place)

__device__ __forceinline__ float warp_sum(float v) {
#pragma unroll
  for (int o = 16; o > 0; o >>= 1) v += __shfl_xor_sync(0xffffffffu, v, o);
  return v;
}

// ======================= mma.sync helpers ===================================
__device__ __forceinline__ uint32_t smem_u32(const void* p) {
  uint32_t a;
  asm("{ .reg .u64 t; cvta.to.shared.u64 t, %1; cvt.u32.u64 %0, t; }"
      : "=r"(a) : "l"(p));
  return a;
}

__device__ __forceinline__ uint32_t tf32u(float a) {
  uint32_t r; asm("cvt.rna.tf32.f32 %0, %1;" : "=r"(r) : "f"(a)); return r;
}

__device__ __forceinline__ void split2(float x, uint32_t& hi, uint32_t& lo) {
  hi = tf32u(x);
  lo = tf32u(x - __uint_as_float(hi));
}

__device__ __forceinline__ void mma_tf32(float* c, const uint32_t* a,
                                         const uint32_t* b) {
  asm volatile(
      "mma.sync.aligned.m16n8k8.row.col.f32.tf32.tf32.f32 "
      "{%0,%1,%2,%3}, {%4,%5,%6,%7}, {%8,%9}, {%0,%1,%2,%3};"
      : "+f"(c[0]), "+f"(c[1]), "+f"(c[2]), "+f"(c[3])
      : "r"(a[0]), "r"(a[1]), "r"(a[2]), "r"(a[3]), "r"(b[0]), "r"(b[1]));
}

__device__ __forceinline__ void mma_bf16(float* c, const uint32_t* a,
                                         const uint32_t* b) {
  asm volatile(
      "mma.sync.aligned.m16n8k16.row.col.f32.bf16.bf16.f32 "
      "{%0,%1,%2,%3}, {%4,%5,%6,%7}, {%8,%9}, {%0,%1,%2,%3};"
      : "+f"(c[0]), "+f"(c[1]), "+f"(c[2]), "+f"(c[3])
      : "r"(a[0]), "r"(a[1]), "r"(a[2]), "r"(a[3]), "r"(b[0]), "r"(b[1]));
}

// pack (elem_k+1, elem_k) -> bf16x2 word (low half = elem_k)
__device__ __forceinline__ uint32_t bf16pack(float hi_elem, float lo_elem) {
  uint32_t r;
  asm("cvt.rn.bf16x2.f32 %0, %1, %2;" : "=r"(r) : "f"(hi_elem), "f"(lo_elem));
  return r;
}

__device__ __forceinline__ void cp16(uint32_t dst, const void* src) {
  asm volatile("cp.async.cg.shared.global [%0], [%1], 16;"
               :: "r"(dst), "l"(src) : "memory");
}
#define CP_COMMIT() asm volatile("cp.async.commit_group;" ::: "memory")
#define CP_WAIT0() asm volatile("cp.async.wait_group 0;" ::: "memory")

// ---------------- 1) per-token projections + rk normalize ------------------
__global__ __launch_bounds__(256) void k_proj_small(
    const float* __restrict__ x, const float* __restrict__ Wg,
    const float* __restrict__ Wb, const float* __restrict__ Wa,
    const float* __restrict__ dtb, const float* __restrict__ Alog) {
  __shared__ float xs[Dn];
  int row = blockIdx.x;                  // b*T + t
  const float* xr = x + (size_t)row * Dn;
  for (int i = threadIdx.x; i < Dn; i += 256) xs[i] = xr[i];
  __syncthreads();
  int h = threadIdx.x >> 5, lane = threadIdx.x & 31;
  const float* wg = Wg + h * Dn;
  const float* wb = Wb + h * Dn;
  const float* wa = Wa + h * Dn;
  float sg = 0.f, sb = 0.f, sa = 0.f;
  for (int i = lane; i < Dn; i += 32) {
    float xv = xs[i];
    sg += xv * wg[i]; sb += xv * wb[i]; sa += xv * wa[i];
  }
  sg = warp_sum(sg); sb = warp_sum(sb); sa = warp_sum(sa);
  float ss = 0.f;
  for (int i = lane; i < HDn; i += 32) { float v = xs[h*HDn + i]; ss += v*v; }
  ss = warp_sum(ss);
  float inv = 1.0f / fmaxf(sqrtf(ss), 1e-12f);
  int b = row >> 13, t = row & (Tn - 1);
  size_t bh = (size_t)b * Hn + h;
  float* rko = g_rk + (bh * Tn + t) * HDn;
  for (int i = lane; i < HDn; i += 32) rko[i] = xs[h*HDn + i] * inv;
  if (lane == 0) {
    g_gate[bh*Tn + t] = 1.0f / (1.0f + expf(-sg));
    g_beta[bh*Tn + t] = 1.0f / (1.0f + expf(-sb));
    float z = sa + dtb[h];
    float sp = (z > 20.0f) ? z : log1pf(expf(z));
    g_dec[bh*Tn + t] = -expf(Alog[h]) * sp;
  }
}

// ---------------- 2) in-chunk cumsum of decay ------------------------------
__global__ void k_cumsum() {
  int idx = blockIdx.x;                  // bh*N + n
  int bh = idx >> 7, n = idx & (Nchunk - 1);
  size_t base = (size_t)bh * Tn + (size_t)n * Cn;
  float v = g_dec[base + threadIdx.x];
  int lane = threadIdx.x & 31, w = threadIdx.x >> 5;
#pragma unroll
  for (int o = 1; o < 32; o <<= 1) {
    float u = __shfl_up_sync(0xffffffffu, v, o);
    if (lane >= o) v += u;
  }
  __shared__ float tot;
  if (w == 0 && lane == 31) tot = v;
  __syncthreads();
  if (w == 1) v += tot;
  g_dec[base + threadIdx.x] = v;
}

// ---------------- 3/6) mma.sync bf16 GEMM (3-product split) ----------------
// C = A @ Bw^T. K staged 32 fp32 -> 16 bf16x2 words per row per plane.
#define KCH 32                            // fp32 K per chunk
#define BSTR 20                           // words per row (16 + 4 pad; g*20+t unique mod 32)
#define PLANE (128*BSTR)                  // words per plane
#define STG_W (4*PLANE)                   // Ahi, Alo, Bhi, Blo
#define GM_SMEM (2*STG_W*4)               // double-buffered (81,920 B)

__global__ __launch_bounds__(256) void k_mma(
    const float* __restrict__ Ain, const float* __restrict__ Bw,
    const float* __restrict__ X, float* __restrict__ Out, int mode) {
  extern __shared__ uint32_t su[];
  int tid = threadIdx.x, wid = tid >> 5, lane = tid & 31;
  int n0 = blockIdx.x * 128;
  int m0 = blockIdx.y * 128;
  int wm = wid >> 2, wn = wid & 3;       // warp tile: rows wm*64, cols wn*32
  int g = lane >> 2, t = lane & 3;

  // device-side resolution of the device-global operand (ATS trap otherwise)
  const float* A = (mode == 0) ? Ain : (const float*)g_o;

  float acc[4][4][4];
#pragma unroll
  for (int mi = 0; mi < 4; mi++)
#pragma unroll
    for (int ni = 0; ni < 4; ni++)
#pragma unroll
      for (int r = 0; r < 4; r++) acc[mi][ni][r] = 0.0f;

  int lrow = tid >> 3, lc4 = tid & 7;    // per-q: row = lrow + 32q, 4 fp32 at lc4*4
  float4 pa[4], pb[4];

  auto ldg = [&](int kc) {
#pragma unroll
    for (int q = 0; q < 4; q++) {
      int row = lrow + 32 * q;
      pa[q] = *(const float4*)(A  + (size_t)(m0 + row) * Dn + kc * KCH + lc4 * 4);
      pb[q] = *(const float4*)(Bw + (size_t)(n0 + row) * Dn + kc * KCH + lc4 * 4);
    }
  };
  auto stage = [&](int s) {
    uint32_t* base = su + s * STG_W;
#pragma unroll
    for (int q = 0; q < 4; q++) {
      int row = lrow + 32 * q;
      int off = row * BSTR + lc4 * 2;
      // A plane
      uint32_t h0 = bf16pack(pa[q].y, pa[q].x);
      uint32_t h1 = bf16pack(pa[q].w, pa[q].z);
      float r0 = pa[q].x - __uint_as_float(h0 << 16);
      float r1 = pa[q].y - __uint_as_float(h0 & 0xffff0000u);
      float r2 = pa[q].z - __uint_as_float(h1 << 16);
      float r3 = pa[q].w - __uint_as_float(h1 & 0xffff0000u);
      *(uint2*)(base + off) = make_uint2(h0, h1);
      *(uint2*)(base + PLANE + off) = make_uint2(bf16pack(r1, r0), bf16pack(r3, r2));
      // B plane
      h0 = bf16pack(pb[q].y, pb[q].x);
      h1 = bf16pack(pb[q].w, pb[q].z);
      r0 = pb[q].x - __uint_as_float(h0 << 16);
      r1 = pb[q].y - __uint_as_float(h0 & 0xffff0000u);
      r2 = pb[q].z - __uint_as_float(h1 << 16);
      r3 = pb[q].w - __uint_as_float(h1 & 0xffff0000u);
      *(uint2*)(base + 2*PLANE + off) = make_uint2(h0, h1);
      *(uint2*)(base + 3*PLANE + off) = make_uint2(bf16pack(r1, r0), bf16pack(r3, r2));
    }
  };

  const int NC = Dn / KCH;               // 32 chunks
  ldg(0); stage(0);
  __syncthreads();
  for (int kc = 0; kc < NC; kc++) {
    int s = kc & 1;
    if (kc + 1 < NC) ldg(kc + 1);        // LDG latency hides under MMA below
    const uint32_t* Ahi = su + s * STG_W;
    const uint32_t* Alo = Ahi + PLANE;
    const uint32_t* Bhi = Alo + PLANE;
    const uint32_t* Blo = Bhi + PLANE;
#pragma unroll
    for (int kk = 0; kk < 2; kk++) {     // K=16 per step
      uint32_t ah[4][4], al[4][4];
#pragma unroll
      for (int mi = 0; mi < 4; mi++) {
        int r0 = wm * 64 + mi * 16 + g;
        int o0 = r0 * BSTR + kk * 8 + t;
        int o1 = (r0 + 8) * BSTR + kk * 8 + t;
        ah[mi][0] = Ahi[o0]; ah[mi][1] = Ahi[o1];
        ah[mi][2] = Ahi[o0 + 4]; ah[mi][3] = Ahi[o1 + 4];
        al[mi][0] = Alo[o0]; al[mi][1] = Alo[o1];
        al[mi][2] = Alo[o0 + 4]; al[mi][3] = Alo[o1 + 4];
      }
      uint32_t bh[4][2], bl[4][2];
#pragma unroll
      for (int ni = 0; ni < 4; ni++) {
        int r0 = wn * 32 + ni * 8 + g;
        int o0 = r0 * BSTR + kk * 8 + t;
        bh[ni][0] = Bhi[o0]; bh[ni][1] = Bhi[o0 + 4];
        bl[ni][0] = Blo[o0]; bl[ni][1] = Blo[o0 + 4];
      }
#pragma unroll
      for (int mi = 0; mi < 4; mi++)
#pragma unroll
        for (int ni = 0; ni < 4; ni++) {
          mma_bf16(acc[mi][ni], ah[mi], bh[ni]);
          mma_bf16(acc[mi][ni], ah[mi], bl[ni]);
          mma_bf16(acc[mi][ni], al[mi], bh[ni]);
        }
    }
    if (kc + 1 < NC) stage(s ^ 1);       // buffer s^1 was consumed in kc-1
    __syncthreads();
  }

  int h = blockIdx.x;                     // mode 0: 128-wide n-block == head
#pragma unroll
  for (int mi = 0; mi < 4; mi++) {
#pragma unroll
    for (int rr = 0; rr < 2; rr++) {
      int m = m0 + wm * 64 + mi * 16 + g + rr * 8;
      if (mode == 0) {
        int b = m >> 13, tt = m & (Tn - 1);
        size_t bhT = ((size_t)(b * Hn + h)) * Tn + tt;
        float beta = g_beta[bhT];
        float* vout = g_v + bhT * HDn;
#pragma unroll
        for (int ni = 0; ni < 4; ni++) {
          int col = wn * 32 + ni * 8 + 2 * t;
          float2 val;
          val.x = acc[mi][ni][rr * 2 + 0] * beta;
          val.y = acc[mi][ni][rr * 2 + 1] * beta;
          *(float2*)(vout + col) = val;
        }
      } else {
#pragma unroll
        for (int ni = 0; ni < 4; ni++) {
          int ncol = n0 + wn * 32 + ni * 8 + 2 * t;
          size_t off = (size_t)m * Dn + ncol;
          float2 xv = *(const float2*)(X + off);
          float2 val;
          val.x = xv.x + acc[mi][ni][rr * 2 + 0];
          val.y = xv.y + acc[mi][ni][rr * 2 + 1];
          *(float2*)(Out + off) = val;
        }
      }
    }
  }
}

// ---------------- 4) per-chunk: P (mma), M, (I+M)^-1, wkcd/v' (mma) --------
#define RS 132
#define K4_SMEM ((65*RS + 2*64*65 + 4*64) * 4)
__global__ __launch_bounds__(256) void k_chunk() {
  extern __shared__ float smf[];
  float* rbuf  = smf;                    // 65 x 132: row0 = wk0, rows1..64 = rk; later v
  float* Msm   = rbuf + 65*RS;           // 64 x 65
  float* Asm   = Msm + 64*65;            // 64 x 65 (P' lower, then inverse)
  float* decS  = Asm + 64*65;            // 64
  float* betaS = decS + 64;
  float* facS  = betaS + 64;             // beta_i * exp(dec_i - dec_{i-1})
  float* beS   = facS + 64;

  int cid = blockIdx.x;                  // bh*N + n
  int bh = cid >> 7, n = cid & (Nchunk - 1);
  int tid = threadIdx.x;
  int wid = tid >> 5, lane = tid & 31;
  int g = lane >> 2, t = lane & 3;
  size_t tbase = (size_t)bh * Tn + (size_t)n * Cn;
  const float* rkG = g_rk + tbase * HDn;

  for (int i = tid; i < 64*128; i += 256) {
    int c = i >> 7, d = i & 127;
    rbuf[(c+1)*RS + d] = rkG[(size_t)c*HDn + d];
  }
  if (tid < 128) rbuf[tid] = (n == 0) ? 0.0f : g_rk[(tbase - 1) * HDn + tid];
  if (tid >= 128 && tid < 192) {
    int c = tid - 128;
    float dv = g_dec[tbase + c];
    float bv = g_beta[tbase + c];
    decS[c] = dv; betaS[c] = bv; beS[c] = bv * __expf(dv);
  }
  __syncthreads();
  if (tid < 64) facS[tid] = (tid == 0) ? 0.0f
                          : betaS[tid] * __expf(decS[tid] - decS[tid-1]);

  // ---- P[i][j] = rk_i . wk_j via mma (3xTF32); wk_j = rbuf row j ----------
  int wr = wid >> 2, wc = wid & 3;       // 2 x 4 warp grid over 64x64
  float pacc[2][2][4];
#pragma unroll
  for (int mi = 0; mi < 2; mi++)
#pragma unroll
    for (int ni = 0; ni < 2; ni++)
#pragma unroll
      for (int r = 0; r < 4; r++) pacc[mi][ni][r] = 0.0f;

#pragma unroll 2
  for (int ks = 0; ks < 16; ks++) {
    int col = ks*8 + t;
    uint32_t ah[2][4], al[2][4];
#pragma unroll
    for (int mi = 0; mi < 2; mi++) {
      int r0 = 1 + wr*32 + mi*16 + g;
      split2(rbuf[r0*RS + col],         ah[mi][0], al[mi][0]);
      split2(rbuf[(r0+8)*RS + col],     ah[mi][1], al[mi][1]);
      split2(rbuf[r0*RS + col + 4],     ah[mi][2], al[mi][2]);
      split2(rbuf[(r0+8)*RS + col + 4], ah[mi][3], al[mi][3]);
    }
    uint32_t bhf[2][2], blf[2][2];
#pragma unroll
    for (int ni = 0; ni < 2; ni++) {
      int nr = wc*16 + ni*8 + g;
      split2(rbuf[nr*RS + col],     bhf[ni][0], blf[ni][0]);
      split2(rbuf[nr*RS + col + 4], bhf[ni][1], blf[ni][1]);
    }
#pragma unroll
    for (int mi = 0; mi < 2; mi++)
#pragma unroll
      for (int ni = 0; ni < 2; ni++) {
        mma_tf32(pacc[mi][ni], ah[mi], bhf[ni]);
        mma_tf32(pacc[mi][ni], ah[mi], blf[ni]);
        mma_tf32(pacc[mi][ni], al[mi], bhf[ni]);
      }
  }

  // epilogue: attn = P * exp(dec_i - dec_j) masked; also P' lower into Asm
  float* attnOut = g_attn + (size_t)cid * 4096;
#pragma unroll
  for (int mi = 0; mi < 2; mi++)
#pragma unroll
    for (int ni = 0; ni < 2; ni++)
#pragma unroll
      for (int r = 0; r < 4; r++) {
        int i = wr*32 + mi*16 + g + ((r & 2) ? 8 : 0);
        int j = wc*16 + ni*8 + 2*t + (r & 1);
        float aval = 0.0f;
        if (i >= j) {
          aval = pacc[mi][ni][r] * __expf(decS[i] - decS[j]);
          Asm[i*65 + j] = aval;
        }
        attnOut[i*64 + j] = aval;
      }
  __syncthreads();

  // M[i][j] (strict lower) = P'[i-1][j] * beta_i * exp(dec_i - dec_{i-1})
  for (int idx = tid; idx < 4096; idx += 256) {
    int i = idx >> 6, j = idx & 63;
    if (i > j) Msm[i*65 + j] = Asm[(i-1)*65 + j] * facS[i];
  }
  __syncthreads();

  // A := I (also zeros the upper triangle for the dense mma below)
  for (int idx = tid; idx < 4096; idx += 256) {
    int i = idx >> 6, j = idx & 63;
    Asm[i*65 + j] = (i == j) ? 1.0f : 0.0f;
  }
  __syncthreads();

  // forward elimination: A = (I+M)^-1 (unit lower triangular)
  for (int i = 0; i < 63; i++) {
    int ncols = i + 1;
    int tot = (63 - i) * ncols;
    for (int idx = tid; idx < tot; idx += 256) {
      int q = idx / ncols;
      int ip = i + 1 + q;
      int k = idx - q * ncols;
      Asm[ip*65 + k] -= Msm[ip*65 + i] * Asm[i*65 + k];
    }
    __syncthreads();
  }

  // scale wk rows in place: rbuf row j *= beta_j * exp(dec_j)
  for (int i = tid; i < 64*128; i += 256) {
    int j = i >> 7, d = i & 127;
    rbuf[j*RS + d] *= beS[j];
  }
  __syncthreads();

  // C = Asm @ Xs (64x128, K=64), 3xTF32 mma; Xs rows in rbuf (stride RS)
  int wr2 = wid >> 1, wc2 = wid & 1;
  auto triMul = [&](float* outp) {
    float cacc[8][4];
#pragma unroll
    for (int ni = 0; ni < 8; ni++)
#pragma unroll
      for (int r = 0; r < 4; r++) cacc[ni][r] = 0.0f;
#pragma unroll 1
    for (int ks = 0; ks < 8; ks++) {
      int col = ks*8 + t;
      uint32_t ah4[4], al4[4];
      int r0 = wr2*16 + g;
      split2(Asm[r0*65 + col],       ah4[0], al4[0]);
      split2(Asm[(r0+8)*65 + col],   ah4[1], al4[1]);
      split2(Asm[r0*65 + col+4],     ah4[2], al4[2]);
      split2(Asm[(r0+8)*65 + col+4], ah4[3], al4[3]);
#pragma unroll
      for (int ni = 0; ni < 8; ni++) {
        int nn = wc2*64 + ni*8 + g;
        uint32_t bh2[2], bl2[2];
        split2(rbuf[col*RS + nn],       bh2[0], bl2[0]);
        split2(rbuf[(col+4)*RS + nn],   bh2[1], bl2[1]);
        mma_tf32(cacc[ni], ah4, bh2);
        mma_tf32(cacc[ni], ah4, bl2);
        mma_tf32(cacc[ni], al4, bh2);
      }
    }
#pragma unroll
    for (int ni = 0; ni < 8; ni++)
#pragma unroll
      for (int rr = 0; rr < 2; rr++) {
        int c = wr2*16 + g + rr*8;
        int d = wc2*64 + ni*8 + 2*t;
        float2 val;
        val.x = cacc[ni][rr*2 + 0];
        val.y = cacc[ni][rr*2 + 1];
        *(float2*)(outp + (size_t)c*HDn + d) = val;
      }
  };

  // wkcd = A^-1 @ (wk * beta * exp(dec))
  triMul(g_wkcd + tbase * HDn);
  __syncthreads();

  // load v (already *beta) into rbuf rows 0..63
  {
    const float* vG = g_v + tbase * HDn;
    for (int i = tid; i < 64*128; i += 256) {
      int c = i >> 7, d = i & 127;
      rbuf[c*RS + d] = vG[(size_t)c*HDn + d];
    }
  }
  __syncthreads();

  // v' = A^-1 @ v
  triMul(g_v + tbase * HDn);
}

// ---------------- 5) inter-chunk recurrence, tensorized --------------------
// S layouts: d-major, stride 40 (B-operand conflict-free: 8*40 % 32 == 8)
#define SS 40
#define ATS 68
#define K5_SMEM ((3*128*SS + 4*64*SS + 64*ATS + 64*RS + 65*RS + 2*64) * 4)
__global__ __launch_bounds__(256) void k_recur() {
  extern __shared__ float smf[];
  float* S      = smf;                   // 128 x 40 fp32
  float* S_hi   = S     + 128*SS;        // tf32 hi copy
  float* S_lo   = S_hi  + 128*SS;        // tf32 lo copy
  float* vn_hi  = S_lo  + 128*SS;        // 64 x 40
  float* vn_lo  = vn_hi + 64*SS;
  float* vns_hi = vn_lo + 64*SS;         // edw-scaled vn
  float* vns_lo = vns_hi+ 64*SS;
  float* attnS  = vns_lo+ 64*SS;         // 64 x 68
  float* bufA   = attnS + 64*ATS;        // 64 x 132 (wkcd)
  float* bufB   = bufA  + 64*RS;         // 65 x 132 (row0=wk0, 1..64=rk)
  float* edwS   = bufB  + 65*RS;         // 64
  float* edcS   = edwS  + 64;            // 64

  uint32_t smb = smem_u32(smf);
  int blk = blockIdx.x;                  // bh*4 + eg
  int bh = blk >> 2, eg = blk & 3;
  int e0 = eg * 32;
  int b = bh >> 3, h = bh & 7;
  int tid = threadIdx.x;
  int wid = tid >> 5, lane = tid & 31;
  int g = lane >> 2, t = lane & 3;

  for (int i = tid; i < 3*128*SS; i += 256) S[i] = 0.0f;
  __syncthreads();

  uint32_t sm_attn = smb + (uint32_t)((attnS - smf) * 4);
  uint32_t sm_bufA = smb + (uint32_t)((bufA - smf) * 4);
  uint32_t sm_bufB = smb + (uint32_t)((bufB - smf) * 4);

  for (int n = 0; n < Nchunk; n++) {
    size_t tbase = (size_t)bh * Tn + (size_t)n * Cn;
    // ---- loads (cp.async) ----
    {
      const float* aG = g_attn + ((size_t)bh * Nchunk + n) * 4096;
#pragma unroll
      for (int q = 0; q < 4; q++) {
        int idx = q * 256 + tid;
        int r = idx >> 4, c4 = idx & 15;
        cp16(sm_attn + (uint32_t)(r * ATS + c4 * 4) * 4, aG + r * 64 + c4 * 4);
      }
      const float* wkcdG = g_wkcd + tbase * HDn;
      const float* rkG = g_rk + tbase * HDn;
#pragma unroll
      for (int q = 0; q < 8; q++) {
        int idx = q * 256 + tid;
        int r = idx >> 5, c4 = idx & 31;
        cp16(sm_bufA + (uint32_t)(r * RS + c4 * 4) * 4,
             wkcdG + (size_t)r * HDn + c4 * 4);
        cp16(sm_bufB + (uint32_t)((r + 1) * RS + c4 * 4) * 4,
             rkG + (size_t)r * HDn + c4 * 4);
      }
      if (tid < 32) {
        if (n == 0) {
          float4 z = make_float4(0.f, 0.f, 0.f, 0.f);
          *(float4*)(bufB + tid * 4) = z;
        } else {
          cp16(sm_bufB + (uint32_t)(tid * 4) * 4,
               g_rk + (tbase - 1) * HDn + tid * 4);
        }
      }
      if (tid < 64) {
        float dv = g_dec[tbase + tid];
        float d63 = g_dec[tbase + 63];
        edcS[tid] = __expf(dv);
        edwS[tid] = __expf(d63 - dv);
      }
      CP_COMMIT(); CP_WAIT0();
    }
    __syncthreads();   // sync 1: tiles + S (from prev chunk) visible

    // ---- phase A: warps 0-3 vnew = v' - wkcd@S ; warps 4-7 oS = rk@S -----
    float acc[4][4];
    int w4 = wid & 3;
    int m0 = w4 * 16;
    bool isV = (wid < 4);
    if (isV) {
      const float* vG = g_v + tbase * HDn;
#pragma unroll
      for (int ni = 0; ni < 4; ni++) {
        int e = ni * 8 + 2 * t;
        float2 p0 = *(const float2*)(vG + (size_t)(m0 + g) * HDn + e0 + e);
        float2 p1 = *(const float2*)(vG + (size_t)(m0 + 8 + g) * HDn + e0 + e);
        acc[ni][0] = p0.x; acc[ni][1] = p0.y;
        acc[ni][2] = p1.x; acc[ni][3] = p1.y;
      }
    } else {
#pragma unroll
      for (int ni = 0; ni < 4; ni++)
#pragma unroll
        for (int r = 0; r < 4; r++) acc[ni][r] = 0.0f;
    }
    {
      const float* Abuf = isV ? bufA : (bufB + RS);  // rk rows offset by 1
      float sgn = isV ? -1.0f : 1.0f;
#pragma unroll 2
      for (int ks = 0; ks < 16; ks++) {
        int k0 = ks * 8;
        uint32_t ah[4], al[4];
        split2(sgn * Abuf[(m0 + g) * RS + k0 + t],         ah[0], al[0]);
        split2(sgn * Abuf[(m0 + 8 + g) * RS + k0 + t],     ah[1], al[1]);
        split2(sgn * Abuf[(m0 + g) * RS + k0 + t + 4],     ah[2], al[2]);
        split2(sgn * Abuf[(m0 + 8 + g) * RS + k0 + t + 4], ah[3], al[3]);
#pragma unroll
        for (int ni = 0; ni < 4; ni++) {
          int nn = ni * 8 + g;
          uint32_t bh2[2], bl2[2];
          bh2[0] = __float_as_uint(S_hi[(k0 + t) * SS + nn]);
          bh2[1] = __float_as_uint(S_hi[(k0 + t + 4) * SS + nn]);
          bl2[0] = __float_as_uint(S_lo[(k0 + t) * SS + nn]);
          bl2[1] = __float_as_uint(S_lo[(k0 + t + 4) * SS + nn]);
          mma_tf32(acc[ni], ah, bh2);
          mma_tf32(acc[ni], ah, bl2);
          mma_tf32(acc[ni], al, bh2);
        }
      }
    }
    if (isV) {
#pragma unroll
      for (int ni = 0; ni < 4; ni++)
#pragma unroll
        for (int r = 0; r < 4; r++) {
          int c = m0 + g + ((r & 2) ? 8 : 0);
          int e = ni * 8 + 2 * t + (r & 1);
          float v = acc[ni][r];
          uint32_t hh, ll;
          split2(v, hh, ll);
          vn_hi[c * SS + e] = __uint_as_float(hh);
          vn_lo[c * SS + e] = __uint_as_float(ll);
          float vs = v * edwS[c];
          split2(vs, hh, ll);
          vns_hi[c * SS + e] = __uint_as_float(hh);
          vns_lo[c * SS + e] = __uint_as_float(ll);
        }
    } else {
#pragma unroll
      for (int ni = 0; ni < 4; ni++) {
        acc[ni][0] *= edcS[m0 + g];     acc[ni][1] *= edcS[m0 + g];
        acc[ni][2] *= edcS[m0 + 8 + g]; acc[ni][3] *= edcS[m0 + 8 + g];
      }
    }
    __syncthreads();   // sync 2: vn arrays visible

    if (!isV) {
      // ---- phase B (warps 4-7): o = oS_scaled + attn @ vn; gated store ----
#pragma unroll 1
      for (int ks = 0; ks < 8; ks++) {
        int k0 = ks * 8;
        uint32_t ah[4], al[4];
        split2(attnS[(m0 + g) * ATS + k0 + t],         ah[0], al[0]);
        split2(attnS[(m0 + 8 + g) * ATS + k0 + t],     ah[1], al[1]);
        split2(attnS[(m0 + g) * ATS + k0 + t + 4],     ah[2], al[2]);
        split2(attnS[(m0 + 8 + g) * ATS + k0 + t + 4], ah[3], al[3]);
#pragma unroll
        for (int ni = 0; ni < 4; ni++) {
          int nn = ni * 8 + g;
          uint32_t bh2[2], bl2[2];
          bh2[0] = __float_as_uint(vn_hi[(k0 + t) * SS + nn]);
          bh2[1] = __float_as_uint(vn_hi[(k0 + t + 4) * SS + nn]);
          bl2[0] = __float_as_uint(vn_lo[(k0 + t) * SS + nn]);
          bl2[1] = __float_as_uint(vn_lo[(k0 + t + 4) * SS + nn]);
          mma_tf32(acc[ni], ah, bh2);
          mma_tf32(acc[ni], ah, bl2);
          mma_tf32(acc[ni], al, bh2);
        }
      }
#pragma unroll
      for (int rr = 0; rr < 2; rr++) {
        int c = m0 + g + rr * 8;
        int tg = n * Cn + c;
        float gate = g_gate[(size_t)bh * Tn + tg];
        float* op = g_o + ((size_t)b * Tn + tg) * Dn + h * HDn + e0;
#pragma unroll
        for (int ni = 0; ni < 4; ni++) {
          float2 val;
          val.x = acc[ni][rr * 2 + 0] * gate;
          val.y = acc[ni][rr * 2 + 1] * gate;
          *(float2*)(op + ni * 8 + 2 * t) = val;
        }
      }
    } else {
      // ---- update (warps 0-3): S = gl*S + wk^T @ vns -----------------------
      int m0u = w4 * 32;
      float acc2[2][4][4];
#pragma unroll
      for (int mi = 0; mi < 2; mi++)
#pragma unroll
        for (int ni = 0; ni < 4; ni++)
#pragma unroll
          for (int r = 0; r < 4; r++) acc2[mi][ni][r] = 0.0f;
#pragma unroll 1
      for (int ks = 0; ks < 8; ks++) {
        int k0 = ks * 8;
        uint32_t ah[2][4], al[2][4];
#pragma unroll
        for (int mi = 0; mi < 2; mi++) {
          int mm = m0u + mi * 16 + g;
          split2(bufB[(k0 + t) * RS + mm],         ah[mi][0], al[mi][0]);
          split2(bufB[(k0 + t) * RS + mm + 8],     ah[mi][1], al[mi][1]);
          split2(bufB[(k0 + t + 4) * RS + mm],     ah[mi][2], al[mi][2]);
          split2(bufB[(k0 + t + 4) * RS + mm + 8], ah[mi][3], al[mi][3]);
        }
#pragma unroll
        for (int ni = 0; ni < 4; ni++) {
          int nn = ni * 8 + g;
          uint32_t bh2[2], bl2[2];
          bh2[0] = __float_as_uint(vns_hi[(k0 + t) * SS + nn]);
          bh2[1] = __float_as_uint(vns_hi[(k0 + t + 4) * SS + nn]);
          bl2[0] = __float_as_uint(vns_lo[(k0 + t) * SS + nn]);
          bl2[1] = __float_as_uint(vns_lo[(k0 + t + 4) * SS + nn]);
#pragma unroll
          for (int mi = 0; mi < 2; mi++) {
            mma_tf32(acc2[mi][ni], ah[mi], bh2);
            mma_tf32(acc2[mi][ni], ah[mi], bl2);
            mma_tf32(acc2[mi][ni], al[mi], bh2);
          }
        }
      }
      float gl = edcS[63];
#pragma unroll
      for (int mi = 0; mi < 2; mi++)
#pragma unroll
        for (int ni = 0; ni < 4; ni++)
#pragma unroll
          for (int r = 0; r < 4; r++) {
            int d = m0u + mi * 16 + g + ((r & 2) ? 8 : 0);
            int e = ni * 8 + 2 * t + (r & 1);
            float sNew = gl * S[d * SS + e] + acc2[mi][ni][r];
            S[d * SS + e] = sNew;
            uint32_t hh, ll;
            split2(sNew, hh, ll);
            S_hi[d * SS + e] = __uint_as_float(hh);
            S_lo[d * SS + e] = __uint_as_float(ll);
          }
    }
    __syncthreads();   // sync 3: S updated; attn/bufs free for next loads
  }
}

// ---------------------------------------------------------------------------
extern "C" void kernel_launch(void* const* d_in, const int* in_sizes, int n_in,
                              void* d_out, int out_size) {
  (void)in_sizes; (void)n_in; (void)out_size;
  const float* x    = (const float*)d_in[0];
  const float* Ww   = (const float*)d_in[1];
  const float* Wg   = (const float*)d_in[2];
  const float* Wo   = (const float*)d_in[3];
  const float* Wb   = (const float*)d_in[4];
  const float* Wa   = (const float*)d_in[5];
  const float* dtb  = (const float*)d_in[6];
  const float* Alog = (const float*)d_in[7];
  float* out = (float*)d_out;

  cudaFuncSetAttribute(k_mma, cudaFuncAttributeMaxDynamicSharedMemorySize, GM_SMEM);
  cudaFuncSetAttribute(k_chunk, cudaFuncAttributeMaxDynamicSharedMemorySize, K4_SMEM);
  cudaFuncSetAttribute(k_recur, cudaFuncAttributeMaxDynamicSharedMemorySize, K5_SMEM);

  k_proj_small<<<BTn, 256>>>(x, Wg, Wb, Wa, dtb, Alog);
  k_cumsum<<<BHn * Nchunk, 64>>>();
  k_mma<<<dim3(Dn/128, BTn/128), 256, GM_SMEM>>>(x, Ww, x, nullptr, 0);
  k_chunk<<<BHn * Nchunk, 256, K4_SMEM>>>();
  k_recur<<<BHn * 4, 256, K5_SMEM>>>();
  k_mma<<<dim3(Dn/128, BTn/128), 256, GM_SMEM>>>(nullptr, Wo, x, out, 1);
}

// round 13
// speedup vs baseline: 1.3892x; 1.0419x over previous
#include <cuda_runtime.h>
#include <math.h>
#include <stdint.h>

#define Bn 4
#define Tn 8192
#define Dn 1024
#define Hn 8
#define HDn 128
#define Cn 64
#define Nchunk 128
#define BTn (Bn*Tn)
#define BHn (Bn*Hn)

// ---------------- scratch (device globals; no cudaMalloc allowed) ----------
__device__ float g_v[(size_t)BTn*Dn];       // v*beta -> v' (in place)
__device__ float g_rk[(size_t)BTn*Dn];      // normalized read keys, (B,H,T,d)
__device__ float g_wkcd[(size_t)BTn*Dn];    // wk_cumdecay, (B,H,T,d)
__device__ float g_o[(size_t)BTn*Dn];       // gated per-head output, (B,T,D)
__device__ float g_attn[(size_t)BHn*Nchunk*Cn*Cn];
__device__ float g_beta[BHn*Tn];            // (B,H,T)
__device__ float g_gate[BHn*Tn];
__device__ float g_dec[BHn*Tn];             // decay, then in-chunk cumsum (in place)

__device__ __forceinline__ float warp_sum(float v) {
#pragma unroll
  for (int o = 16; o > 0; o >>= 1) v += __shfl_xor_sync(0xffffffffu, v, o);
  return v;
}

// ======================= mma.sync helpers ===================================
__device__ __forceinline__ uint32_t smem_u32(const void* p) {
  uint32_t a;
  asm("{ .reg .u64 t; cvta.to.shared.u64 t, %1; cvt.u32.u64 %0, t; }"
      : "=r"(a) : "l"(p));
  return a;
}

__device__ __forceinline__ uint32_t tf32u(float a) {
  uint32_t r; asm("cvt.rna.tf32.f32 %0, %1;" : "=r"(r) : "f"(a)); return r;
}

__device__ __forceinline__ void split2(float x, uint32_t& hi, uint32_t& lo) {
  hi = tf32u(x);
  lo = tf32u(x - __uint_as_float(hi));
}

__device__ __forceinline__ void mma_tf32(float* c, const uint32_t* a,
                                         const uint32_t* b) {
  asm volatile(
      "mma.sync.aligned.m16n8k8.row.col.f32.tf32.tf32.f32 "
      "{%0,%1,%2,%3}, {%4,%5,%6,%7}, {%8,%9}, {%0,%1,%2,%3};"
      : "+f"(c[0]), "+f"(c[1]), "+f"(c[2]), "+f"(c[3])
      : "r"(a[0]), "r"(a[1]), "r"(a[2]), "r"(a[3]), "r"(b[0]), "r"(b[1]));
}

__device__ __forceinline__ void mma_bf16(float* c, const uint32_t* a,
                                         const uint32_t* b) {
  asm volatile(
      "mma.sync.aligned.m16n8k16.row.col.f32.bf16.bf16.f32 "
      "{%0,%1,%2,%3}, {%4,%5,%6,%7}, {%8,%9}, {%0,%1,%2,%3};"
      : "+f"(c[0]), "+f"(c[1]), "+f"(c[2]), "+f"(c[3])
      : "r"(a[0]), "r"(a[1]), "r"(a[2]), "r"(a[3]), "r"(b[0]), "r"(b[1]));
}

// pack (elem_k+1, elem_k) -> bf16x2 word (low half = elem_k)
__device__ __forceinline__ uint32_t bf16pack(float hi_elem, float lo_elem) {
  uint32_t r;
  asm("cvt.rn.bf16x2.f32 %0, %1, %2;" : "=r"(r) : "f"(hi_elem), "f"(lo_elem));
  return r;
}

// split a float pair into hi word + lo (residual) word
__device__ __forceinline__ void packsplit(float x0, float x1,
                                          uint32_t& wh, uint32_t& wl) {
  wh = bf16pack(x1, x0);
  float q0 = x0 - __uint_as_float(wh << 16);
  float q1 = x1 - __uint_as_float(wh & 0xffff0000u);
  wl = bf16pack(q1, q0);
}

__device__ __forceinline__ void cp16(uint32_t dst, const void* src) {
  asm volatile("cp.async.cg.shared.global [%0], [%1], 16;"
               :: "r"(dst), "l"(src) : "memory");
}
#define CP_COMMIT() asm volatile("cp.async.commit_group;" ::: "memory")
#define CP_WAIT0() asm volatile("cp.async.wait_group 0;" ::: "memory")

// ---------------- 1) per-token projections + rk normalize ------------------
__global__ __launch_bounds__(256) void k_proj_small(
    const float* __restrict__ x, const float* __restrict__ Wg,
    const float* __restrict__ Wb, const float* __restrict__ Wa,
    const float* __restrict__ dtb, const float* __restrict__ Alog) {
  __shared__ float xs[Dn];
  int row = blockIdx.x;                  // b*T + t
  const float* xr = x + (size_t)row * Dn;
  for (int i = threadIdx.x; i < Dn; i += 256) xs[i] = xr[i];
  __syncthreads();
  int h = threadIdx.x >> 5, lane = threadIdx.x & 31;
  const float* wg = Wg + h * Dn;
  const float* wb = Wb + h * Dn;
  const float* wa = Wa + h * Dn;
  float sg = 0.f, sb = 0.f, sa = 0.f;
  for (int i = lane; i < Dn; i += 32) {
    float xv = xs[i];
    sg += xv * wg[i]; sb += xv * wb[i]; sa += xv * wa[i];
  }
  sg = warp_sum(sg); sb = warp_sum(sb); sa = warp_sum(sa);
  float ss = 0.f;
  for (int i = lane; i < HDn; i += 32) { float v = xs[h*HDn + i]; ss += v*v; }
  ss = warp_sum(ss);
  float inv = 1.0f / fmaxf(sqrtf(ss), 1e-12f);
  int b = row >> 13, t = row & (Tn - 1);
  size_t bh = (size_t)b * Hn + h;
  float* rko = g_rk + (bh * Tn + t) * HDn;
  for (int i = lane; i < HDn; i += 32) rko[i] = xs[h*HDn + i] * inv;
  if (lane == 0) {
    g_gate[bh*Tn + t] = 1.0f / (1.0f + expf(-sg));
    g_beta[bh*Tn + t] = 1.0f / (1.0f + expf(-sb));
    float z = sa + dtb[h];
    float sp = (z > 20.0f) ? z : log1pf(expf(z));
    g_dec[bh*Tn + t] = -expf(Alog[h]) * sp;
  }
}

// ---------------- 2) in-chunk cumsum of decay ------------------------------
__global__ void k_cumsum() {
  int idx = blockIdx.x;                  // bh*N + n
  int bh = idx >> 7, n = idx & (Nchunk - 1);
  size_t base = (size_t)bh * Tn + (size_t)n * Cn;
  float v = g_dec[base + threadIdx.x];
  int lane = threadIdx.x & 31, w = threadIdx.x >> 5;
#pragma unroll
  for (int o = 1; o < 32; o <<= 1) {
    float u = __shfl_up_sync(0xffffffffu, v, o);
    if (lane >= o) v += u;
  }
  __shared__ float tot;
  if (w == 0 && lane == 31) tot = v;
  __syncthreads();
  if (w == 1) v += tot;
  g_dec[base + threadIdx.x] = v;
}

// ---------------- 3/6) mma.sync bf16 GEMM, cp.async landing, 2 CTA/SM ------
#define KCH 32                            // fp32 K per chunk
#define LSTR 36                           // landing stride (f32)
#define LAND_F (2*128*LSTR)               // A+B landing = 9216 floats
#define BSTR 20                           // plane words/row (16 + 4 pad)
#define PLANE (128*BSTR)                  // 2560 words
#define GM_SMEM ((LAND_F + 4*PLANE)*4)    // 77,824 B -> 2 CTAs/SM

__global__ __launch_bounds__(256, 2) void k_mma(
    const float* __restrict__ Ain, const float* __restrict__ Bw,
    const float* __restrict__ X, float* __restrict__ Out, int mode) {
  extern __shared__ float sf[];
  float* land = sf;
  uint32_t* pl = (uint32_t*)(sf + LAND_F);
  uint32_t land_u = smem_u32(sf);
  int tid = threadIdx.x, wid = tid >> 5, lane = tid & 31;
  int n0 = blockIdx.x * 128;
  int m0 = blockIdx.y * 128;
  int wm = wid >> 2, wn = wid & 3;       // warp tile: rows wm*64, cols wn*32
  int g = lane >> 2, t = lane & 3;

  // device-side resolution of the device-global operand (ATS trap otherwise)
  const float* A = (mode == 0) ? Ain : (const float*)g_o;

  float acc[4][4][4];
#pragma unroll
  for (int mi = 0; mi < 4; mi++)
#pragma unroll
    for (int ni = 0; ni < 4; ni++)
#pragma unroll
      for (int r = 0; r < 4; r++) acc[mi][ni][r] = 0.0f;

  int lrow = tid >> 3, lc4 = tid & 7;

  auto cp_issue = [&](int kc) {
#pragma unroll
    for (int q = 0; q < 4; q++) {
      int row = lrow + 32 * q;
      cp16(land_u + (uint32_t)(row * LSTR + lc4 * 4) * 4,
           A + (size_t)(m0 + row) * Dn + kc * KCH + lc4 * 4);
      cp16(land_u + (uint32_t)((128 + row) * LSTR + lc4 * 4) * 4,
           Bw + (size_t)(n0 + row) * Dn + kc * KCH + lc4 * 4);
    }
    CP_COMMIT();
  };
  auto stage = [&]() {
#pragma unroll
    for (int q = 0; q < 4; q++) {
      int row = lrow + 32 * q;
      float4 va = *(const float4*)(land + row * LSTR + lc4 * 4);
      float4 vb = *(const float4*)(land + (128 + row) * LSTR + lc4 * 4);
      int off = row * BSTR + lc4 * 2;
      uint32_t h0, l0, h1, l1;
      packsplit(va.x, va.y, h0, l0);
      packsplit(va.z, va.w, h1, l1);
      *(uint2*)(pl + off) = make_uint2(h0, h1);
      *(uint2*)(pl + PLANE + off) = make_uint2(l0, l1);
      packsplit(vb.x, vb.y, h0, l0);
      packsplit(vb.z, vb.w, h1, l1);
      *(uint2*)(pl + 2*PLANE + off) = make_uint2(h0, h1);
      *(uint2*)(pl + 3*PLANE + off) = make_uint2(l0, l1);
    }
  };

  const int NC = Dn / KCH;               // 32 chunks
  cp_issue(0);
  CP_WAIT0();                            // own data landed (same-thread mapping)
  for (int kc = 0; kc < NC; kc++) {
    stage();
    __syncthreads();                     // planes visible; land fully read
    if (kc + 1 < NC) cp_issue(kc + 1);
    const uint32_t* Ahi = pl;
    const uint32_t* Alo = Ahi + PLANE;
    const uint32_t* Bhi = Alo + PLANE;
    const uint32_t* Blo = Bhi + PLANE;
#pragma unroll
    for (int kk = 0; kk < 2; kk++) {     // K=16 per step
      uint32_t ah[4][4], al[4][4];
#pragma unroll
      for (int mi = 0; mi < 4; mi++) {
        int r0 = wm * 64 + mi * 16 + g;
        int o0 = r0 * BSTR + kk * 8 + t;
        int o1 = (r0 + 8) * BSTR + kk * 8 + t;
        ah[mi][0] = Ahi[o0]; ah[mi][1] = Ahi[o1];
        ah[mi][2] = Ahi[o0 + 4]; ah[mi][3] = Ahi[o1 + 4];
        al[mi][0] = Alo[o0]; al[mi][1] = Alo[o1];
        al[mi][2] = Alo[o0 + 4]; al[mi][3] = Alo[o1 + 4];
      }
      uint32_t bh[4][2], bl[4][2];
#pragma unroll
      for (int ni = 0; ni < 4; ni++) {
        int r0 = wn * 32 + ni * 8 + g;
        int o0 = r0 * BSTR + kk * 8 + t;
        bh[ni][0] = Bhi[o0]; bh[ni][1] = Bhi[o0 + 4];
        bl[ni][0] = Blo[o0]; bl[ni][1] = Blo[o0 + 4];
      }
#pragma unroll
      for (int mi = 0; mi < 4; mi++)
#pragma unroll
        for (int ni = 0; ni < 4; ni++) {
          mma_bf16(acc[mi][ni], ah[mi], bh[ni]);
          mma_bf16(acc[mi][ni], ah[mi], bl[ni]);
          mma_bf16(acc[mi][ni], al[mi], bh[ni]);
        }
    }
    if (kc + 1 < NC) CP_WAIT0();         // own next-chunk data landed
    __syncthreads();                     // mma done before planes overwritten
  }

  int h = blockIdx.x;                     // mode 0: 128-wide n-block == head
#pragma unroll
  for (int mi = 0; mi < 4; mi++) {
#pragma unroll
    for (int rr = 0; rr < 2; rr++) {
      int m = m0 + wm * 64 + mi * 16 + g + rr * 8;
      if (mode == 0) {
        int b = m >> 13, tt = m & (Tn - 1);
        size_t bhT = ((size_t)(b * Hn + h)) * Tn + tt;
        float beta = g_beta[bhT];
        float* vout = g_v + bhT * HDn;
#pragma unroll
        for (int ni = 0; ni < 4; ni++) {
          int col = wn * 32 + ni * 8 + 2 * t;
          float2 val;
          val.x = acc[mi][ni][rr * 2 + 0] * beta;
          val.y = acc[mi][ni][rr * 2 + 1] * beta;
          *(float2*)(vout + col) = val;
        }
      } else {
#pragma unroll
        for (int ni = 0; ni < 4; ni++) {
          int ncol = n0 + wn * 32 + ni * 8 + 2 * t;
          size_t off = (size_t)m * Dn + ncol;
          float2 xv = *(const float2*)(X + off);
          float2 val;
          val.x = xv.x + acc[mi][ni][rr * 2 + 0];
          val.y = xv.y + acc[mi][ni][rr * 2 + 1];
          *(float2*)(Out + off) = val;
        }
      }
    }
  }
}

// ---------------- 4) per-chunk, all-bf16: P, M(upper), inv, wkcd/v' --------
// kb planes: rows = [w0; rk], K = head dim packed in bf16x2 (64 words + 4 pad)
// tb planes: transposed (K = chunk pairs, n = head dim), stride 136 (8 mod 32)
#define KBS 68
#define TBS 136
#define K4_SMEM ((2*65*KBS + 64*65 + 4*64) * 4)
__global__ __launch_bounds__(256) void k_chunk() {
  extern __shared__ float smf[];
  uint32_t* kbh = (uint32_t*)smf;
  uint32_t* kbl = kbh + 65*KBS;
  uint32_t* tbh = kbh;                   // overlay (P-phase done before use)
  uint32_t* tbl = kbl;
  float* Asm   = smf + 2*65*KBS;         // 64 x 65
  float* decS  = Asm + 64*65;
  float* betaS = decS + 64;
  float* facS  = betaS + 64;
  float* beS   = facS + 64;

  int cid = blockIdx.x;                  // bh*N + n
  int bh = cid >> 7, n = cid & (Nchunk - 1);
  int tid = threadIdx.x;
  int wid = tid >> 5, lane = tid & 31;
  int g = lane >> 2, t = lane & 3;
  size_t tbase = (size_t)bh * Tn + (size_t)n * Cn;
  const float* rkG = g_rk + tbase * HDn;

  if (tid < 64) {
    float dv = g_dec[tbase + tid];
    float bv = g_beta[tbase + tid];
    decS[tid] = dv; betaS[tid] = bv; beS[tid] = bv * __expf(dv);
  }
  // kb planes rows 1..64 = rk rows 0..63
  for (int i = tid; i < 64*64; i += 256) {
    int r1 = i >> 6, w = i & 63;
    float2 v2 = *(const float2*)(rkG + (size_t)r1 * HDn + 2*w);
    uint32_t wh, wl;
    packsplit(v2.x, v2.y, wh, wl);
    kbh[(r1+1)*KBS + w] = wh;
    kbl[(r1+1)*KBS + w] = wl;
  }
  if (tid < 64) {
    float2 v2 = (n == 0) ? make_float2(0.f, 0.f)
                         : *(const float2*)(g_rk + (tbase - 1) * HDn + 2*tid);
    uint32_t wh, wl;
    packsplit(v2.x, v2.y, wh, wl);
    kbh[tid] = wh; kbl[tid] = wl;
  }
  __syncthreads();
  if (tid < 64) facS[tid] = (tid == 0) ? 0.0f
                          : betaS[tid] * __expf(decS[tid] - decS[tid-1]);

  // ---- P[i][j] = rk_i . wk_j via bf16 mma (K=128 -> 8 k16 blocks) ---------
  int wr = wid >> 2, wc = wid & 3;       // 2 x 4 warp grid over 64x64
  float pacc[2][2][4];
#pragma unroll
  for (int mi = 0; mi < 2; mi++)
#pragma unroll
    for (int ni = 0; ni < 2; ni++)
#pragma unroll
      for (int r = 0; r < 4; r++) pacc[mi][ni][r] = 0.0f;

#pragma unroll 1
  for (int ks = 0; ks < 8; ks++) {
    int w1 = ks*8 + t;
    uint32_t ah[2][4], al[2][4];
#pragma unroll
    for (int mi = 0; mi < 2; mi++) {
      int r0 = 1 + wr*32 + mi*16 + g;
      ah[mi][0] = kbh[r0*KBS + w1];     ah[mi][1] = kbh[(r0+8)*KBS + w1];
      ah[mi][2] = kbh[r0*KBS + w1 + 4]; ah[mi][3] = kbh[(r0+8)*KBS + w1 + 4];
      al[mi][0] = kbl[r0*KBS + w1];     al[mi][1] = kbl[(r0+8)*KBS + w1];
      al[mi][2] = kbl[r0*KBS + w1 + 4]; al[mi][3] = kbl[(r0+8)*KBS + w1 + 4];
    }
    uint32_t bhf[2][2], blf[2][2];
#pragma unroll
    for (int ni = 0; ni < 2; ni++) {
      int nr = wc*16 + ni*8 + g;
      bhf[ni][0] = kbh[nr*KBS + w1]; bhf[ni][1] = kbh[nr*KBS + w1 + 4];
      blf[ni][0] = kbl[nr*KBS + w1]; blf[ni][1] = kbl[nr*KBS + w1 + 4];
    }
#pragma unroll
    for (int mi = 0; mi < 2; mi++)
#pragma unroll
      for (int ni = 0; ni < 2; ni++) {
        mma_bf16(pacc[mi][ni], ah[mi], bhf[ni]);
        mma_bf16(pacc[mi][ni], ah[mi], blf[ni]);
        mma_bf16(pacc[mi][ni], al[mi], bhf[ni]);
      }
  }

  // epilogue: attn = P * exp(dec_i - dec_j) masked; P' lower into Asm
  float* attnOut = g_attn + (size_t)cid * 4096;
#pragma unroll
  for (int mi = 0; mi < 2; mi++)
#pragma unroll
    for (int ni = 0; ni < 2; ni++)
#pragma unroll
      for (int r = 0; r < 4; r++) {
        int i = wr*32 + mi*16 + g + ((r & 2) ? 8 : 0);
        int j = wc*16 + ni*8 + 2*t + (r & 1);
        float aval = 0.0f;
        if (i >= j) {
          aval = pacc[mi][ni][r] * __expf(decS[i] - decS[j]);
          Asm[i*65 + j] = aval;
        }
        attnOut[i*64 + j] = aval;
      }
  __syncthreads();

  // M^T into Asm upper: slot(row j, col i) = M[i][j] = P'[i-1][j]*fac[i]
  for (int idx = tid; idx < 4096; idx += 256) {
    int i = idx >> 6, j = idx & 63;
    if (i > j) Asm[j*65 + i] = Asm[(i-1)*65 + j] * facS[i];
  }
  __syncthreads();

  // lower := I (upper keeps M^T)
  for (int idx = tid; idx < 4096; idx += 256) {
    int i = idx >> 6, j = idx & 63;
    if (j <= i) Asm[i*65 + j] = (i == j) ? 1.0f : 0.0f;
  }
  __syncthreads();

  // forward elimination; M read from upper
  for (int i = 0; i < 63; i++) {
    int ncols = i + 1;
    int tot = (63 - i) * ncols;
    for (int idx = tid; idx < tot; idx += 256) {
      int q = idx / ncols;
      int ip = i + 1 + q;
      int k = idx - q * ncols;
      Asm[ip*65 + k] -= Asm[i*65 + ip] * Asm[i*65 + k];
    }
    __syncthreads();
  }

  // zero upper (dense mma A) + stage tb planes with scaled wk (transposed)
  for (int idx = tid; idx < 4096; idx += 256) {
    int i = idx >> 6, j = idx & 63;
    if (j > i) Asm[i*65 + j] = 0.0f;
  }
  for (int i = tid; i < 32*128; i += 256) {
    int w = i >> 7, d = i & 127;
    int j0 = 2*w;
    float x0 = (j0 == 0)
        ? ((n == 0) ? 0.0f : g_rk[(tbase - 1) * HDn + d])
        : rkG[(size_t)(j0 - 1) * HDn + d];
    float x1 = rkG[(size_t)j0 * HDn + d];      // row j1-1 = 2w
    x0 *= beS[j0]; x1 *= beS[j0 + 1];
    uint32_t wh, wl;
    packsplit(x0, x1, wh, wl);
    tbh[w*TBS + d] = wh; tbl[w*TBS + d] = wl;
  }
  __syncthreads();

  // C = Asm @ X (64x128, K=64 -> 4 k16 blocks); A split on the fly
  int wr2 = wid >> 1, wc2 = wid & 1;
  auto triMulBf = [&](float* outp) {
    float cacc[8][4];
#pragma unroll
    for (int ni = 0; ni < 8; ni++)
#pragma unroll
      for (int r = 0; r < 4; r++) cacc[ni][r] = 0.0f;
#pragma unroll 1
    for (int ks = 0; ks < 4; ks++) {
      int w1 = ks*8 + t;
      int r0 = wr2*16 + g;
      uint32_t ah4[4], al4[4];
      packsplit(Asm[r0*65 + 2*w1],       Asm[r0*65 + 2*w1 + 1],       ah4[0], al4[0]);
      packsplit(Asm[(r0+8)*65 + 2*w1],   Asm[(r0+8)*65 + 2*w1 + 1],   ah4[1], al4[1]);
      packsplit(Asm[r0*65 + 2*w1 + 8],   Asm[r0*65 + 2*w1 + 9],       ah4[2], al4[2]);
      packsplit(Asm[(r0+8)*65 + 2*w1+8], Asm[(r0+8)*65 + 2*w1 + 9],   al4[3], al4[3]);
      // fix: recompute ah4[3] properly
      packsplit(Asm[(r0+8)*65 + 2*w1+8], Asm[(r0+8)*65 + 2*w1 + 9],   ah4[3], al4[3]);
#pragma unroll
      for (int ni = 0; ni < 8; ni++) {
        int nn = wc2*64 + ni*8 + g;
        uint32_t b2h[2], b2l[2];
        b2h[0] = tbh[w1*TBS + nn]; b2h[1] = tbh[(w1+4)*TBS + nn];
        b2l[0] = tbl[w1*TBS + nn]; b2l[1] = tbl[(w1+4)*TBS + nn];
        mma_bf16(cacc[ni], ah4, b2h);
        mma_bf16(cacc[ni], ah4, b2l);
        mma_bf16(cacc[ni], al4, b2h);
      }
    }
#pragma unroll
    for (int ni = 0; ni < 8; ni++)
#pragma unroll
      for (int rr = 0; rr < 2; rr++) {
        int c = wr2*16 + g + rr*8;
        int d = wc2*64 + ni*8 + 2*t;
        float2 val;
        val.x = cacc[ni][rr*2 + 0];
        val.y = cacc[ni][rr*2 + 1];
        *(float2*)(outp + (size_t)c*HDn + d) = val;
      }
  };

  // wkcd = A^-1 @ (wk * beta * exp(dec))
  triMulBf(g_wkcd + tbase * HDn);
  __syncthreads();

  // tb <- v (already *beta)
  {
    const float* vG = g_v + tbase * HDn;
    for (int i = tid; i < 32*128; i += 256) {
      int w = i >> 7, d = i & 127;
      float x0 = vG[(size_t)(2*w) * HDn + d];
      float x1 = vG[(size_t)(2*w + 1) * HDn + d];
      uint32_t wh, wl;
      packsplit(x0, x1, wh, wl);
      tbh[w*TBS + d] = wh; tbl[w*TBS + d] = wl;
    }
  }
  __syncthreads();

  // v' = A^-1 @ v
  triMulBf(g_v + tbase * HDn);
}

// ---------------- 5) inter-chunk recurrence, tensorized (tf32) -------------
#define RS 132
#define SS 40
#define ATS 68
#define K5_SMEM ((3*128*SS + 4*64*SS + 64*ATS + 64*RS + 65*RS + 2*64) * 4)
__global__ __launch_bounds__(256) void k_recur() {
  extern __shared__ float smf[];
  float* S      = smf;                   // 128 x 40 fp32
  float* S_hi   = S     + 128*SS;
  float* S_lo   = S_hi  + 128*SS;
  float* vn_hi  = S_lo  + 128*SS;
  float* vn_lo  = vn_hi + 64*SS;
  float* vns_hi = vn_lo + 64*SS;
  float* vns_lo = vns_hi+ 64*SS;
  float* attnS  = vns_lo+ 64*SS;         // 64 x 68
  float* bufA   = attnS + 64*ATS;        // 64 x 132 (wkcd)
  float* bufB   = bufA  + 64*RS;         // 65 x 132 (row0=wk0, 1..64=rk)
  float* edwS   = bufB  + 65*RS;
  float* edcS   = edwS  + 64;

  uint32_t smb = smem_u32(smf);
  int blk = blockIdx.x;                  // bh*4 + eg
  int bh = blk >> 2, eg = blk & 3;
  int e0 = eg * 32;
  int b = bh >> 3, h = bh & 7;
  int tid = threadIdx.x;
  int wid = tid >> 5, lane = tid & 31;
  int g = lane >> 2, t = lane & 3;

  for (int i = tid; i < 3*128*SS; i += 256) S[i] = 0.0f;
  __syncthreads();

  uint32_t sm_attn = smb + (uint32_t)((attnS - smf) * 4);
  uint32_t sm_bufA = smb + (uint32_t)((bufA - smf) * 4);
  uint32_t sm_bufB = smb + (uint32_t)((bufB - smf) * 4);

  for (int n = 0; n < Nchunk; n++) {
    size_t tbase = (size_t)bh * Tn + (size_t)n * Cn;
    {
      const float* aG = g_attn + ((size_t)bh * Nchunk + n) * 4096;
#pragma unroll
      for (int q = 0; q < 4; q++) {
        int idx = q * 256 + tid;
        int r = idx >> 4, c4 = idx & 15;
        cp16(sm_attn + (uint32_t)(r * ATS + c4 * 4) * 4, aG + r * 64 + c4 * 4);
      }
      const float* wkcdG = g_wkcd + tbase * HDn;
      const float* rkG = g_rk + tbase * HDn;
#pragma unroll
      for (int q = 0; q < 8; q++) {
        int idx = q * 256 + tid;
        int r = idx >> 5, c4 = idx & 31;
        cp16(sm_bufA + (uint32_t)(r * RS + c4 * 4) * 4,
             wkcdG + (size_t)r * HDn + c4 * 4);
        cp16(sm_bufB + (uint32_t)((r + 1) * RS + c4 * 4) * 4,
             rkG + (size_t)r * HDn + c4 * 4);
      }
      if (tid < 32) {
        if (n == 0) {
          float4 z = make_float4(0.f, 0.f, 0.f, 0.f);
          *(float4*)(bufB + tid * 4) = z;
        } else {
          cp16(sm_bufB + (uint32_t)(tid * 4) * 4,
               g_rk + (tbase - 1) * HDn + tid * 4);
        }
      }
      if (tid < 64) {
        float dv = g_dec[tbase + tid];
        float d63 = g_dec[tbase + 63];
        edcS[tid] = __expf(dv);
        edwS[tid] = __expf(d63 - dv);
      }
      CP_COMMIT(); CP_WAIT0();
    }
    __syncthreads();

    float acc[4][4];
    int w4 = wid & 3;
    int m0 = w4 * 16;
    bool isV = (wid < 4);
    if (isV) {
      const float* vG = g_v + tbase * HDn;
#pragma unroll
      for (int ni = 0; ni < 4; ni++) {
        int e = ni * 8 + 2 * t;
        float2 p0 = *(const float2*)(vG + (size_t)(m0 + g) * HDn + e0 + e);
        float2 p1 = *(const float2*)(vG + (size_t)(m0 + 8 + g) * HDn + e0 + e);
        acc[ni][0] = p0.x; acc[ni][1] = p0.y;
        acc[ni][2] = p1.x; acc[ni][3] = p1.y;
      }
    } else {
#pragma unroll
      for (int ni = 0; ni < 4; ni++)
#pragma unroll
        for (int r = 0; r < 4; r++) acc[ni][r] = 0.0f;
    }
    {
      const float* Abuf = isV ? bufA : (bufB + RS);
      float sgn = isV ? -1.0f : 1.0f;
#pragma unroll 2
      for (int ks = 0; ks < 16; ks++) {
        int k0 = ks * 8;
        uint32_t ah[4], al[4];
        split2(sgn * Abuf[(m0 + g) * RS + k0 + t],         ah[0], al[0]);
        split2(sgn * Abuf[(m0 + 8 + g) * RS + k0 + t],     ah[1], al[1]);
        split2(sgn * Abuf[(m0 + g) * RS + k0 + t + 4],     ah[2], al[2]);
        split2(sgn * Abuf[(m0 + 8 + g) * RS + k0 + t + 4], ah[3], al[3]);
#pragma unroll
        for (int ni = 0; ni < 4; ni++) {
          int nn = ni * 8 + g;
          uint32_t bh2[2], bl2[2];
          bh2[0] = __float_as_uint(S_hi[(k0 + t) * SS + nn]);
          bh2[1] = __float_as_uint(S_hi[(k0 + t + 4) * SS + nn]);
          bl2[0] = __float_as_uint(S_lo[(k0 + t) * SS + nn]);
          bl2[1] = __float_as_uint(S_lo[(k0 + t + 4) * SS + nn]);
          mma_tf32(acc[ni], ah, bh2);
          mma_tf32(acc[ni], ah, bl2);
          mma_tf32(acc[ni], al, bh2);
        }
      }
    }
    if (isV) {
#pragma unroll
      for (int ni = 0; ni < 4; ni++)
#pragma unroll
        for (int r = 0; r < 4; r++) {
          int c = m0 + g + ((r & 2) ? 8 : 0);
          int e = ni * 8 + 2 * t + (r & 1);
          float v = acc[ni][r];
          uint32_t hh, ll;
          split2(v, hh, ll);
          vn_hi[c * SS + e] = __uint_as_float(hh);
          vn_lo[c * SS + e] = __uint_as_float(ll);
          float vs = v * edwS[c];
          split2(vs, hh, ll);
          vns_hi[c * SS + e] = __uint_as_float(hh);
          vns_lo[c * SS + e] = __uint_as_float(ll);
        }
    } else {
#pragma unroll
      for (int ni = 0; ni < 4; ni++) {
        acc[ni][0] *= edcS[m0 + g];     acc[ni][1] *= edcS[m0 + g];
        acc[ni][2] *= edcS[m0 + 8 + g]; acc[ni][3] *= edcS[m0 + 8 + g];
      }
    }
    __syncthreads();

    if (!isV) {
#pragma unroll 1
      for (int ks = 0; ks < 8; ks++) {
        int k0 = ks * 8;
        uint32_t ah[4], al[4];
        split2(attnS[(m0 + g) * ATS + k0 + t],         ah[0], al[0]);
        split2(attnS[(m0 + 8 + g) * ATS + k0 + t],     ah[1], al[1]);
        split2(attnS[(m0 + g) * ATS + k0 + t + 4],     ah[2], al[2]);
        split2(attnS[(m0 + 8 + g) * ATS + k0 + t + 4], ah[3], al[3]);
#pragma unroll
        for (int ni = 0; ni < 4; ni++) {
          int nn = ni * 8 + g;
          uint32_t bh2[2], bl2[2];
          bh2[0] = __float_as_uint(vn_hi[(k0 + t) * SS + nn]);
          bh2[1] = __float_as_uint(vn_hi[(k0 + t + 4) * SS + nn]);
          bl2[0] = __float_as_uint(vn_lo[(k0 + t) * SS + nn]);
          bl2[1] = __float_as_uint(vn_lo[(k0 + t + 4) * SS + nn]);
          mma_tf32(acc[ni], ah, bh2);
          mma_tf32(acc[ni], ah, bl2);
          mma_tf32(acc[ni], al, bh2);
        }
      }
#pragma unroll
      for (int rr = 0; rr < 2; rr++) {
        int c = m0 + g + rr * 8;
        int tg = n * Cn + c;
        float gate = g_gate[(size_t)bh * Tn + tg];
        float* op = g_o + ((size_t)b * Tn + tg) * Dn + h * HDn + e0;
#pragma unroll
        for (int ni = 0; ni < 4; ni++) {
          float2 val;
          val.x = acc[ni][rr * 2 + 0] * gate;
          val.y = acc[ni][rr * 2 + 1] * gate;
          *(float2*)(op + ni * 8 + 2 * t) = val;
        }
      }
    } else {
      int m0u = w4 * 32;
      float acc2[2][4][4];
#pragma unroll
      for (int mi = 0; mi < 2; mi++)
#pragma unroll
        for (int ni = 0; ni < 4; ni++)
#pragma unroll
          for (int r = 0; r < 4; r++) acc2[mi][ni][r] = 0.0f;
#pragma unroll 1
      for (int ks = 0; ks < 8; ks++) {
        int k0 = ks * 8;
        uint32_t ah[2][4], al[2][4];
#pragma unroll
        for (int mi = 0; mi < 2; mi++) {
          int mm = m0u + mi * 16 + g;
          split2(bufB[(k0 + t) * RS + mm],         ah[mi][0], al[mi][0]);
          split2(bufB[(k0 + t) * RS + mm + 8],     ah[mi][1], al[mi][1]);
          split2(bufB[(k0 + t + 4) * RS + mm],     ah[mi][2], al[mi][2]);
          split2(bufB[(k0 + t + 4) * RS + mm + 8], ah[mi][3], al[mi][3]);
        }
#pragma unroll
        for (int ni = 0; ni < 4; ni++) {
          int nn = ni * 8 + g;
          uint32_t bh2[2], bl2[2];
          bh2[0] = __float_as_uint(vns_hi[(k0 + t) * SS + nn]);
          bh2[1] = __float_as_uint(vns_hi[(k0 + t + 4) * SS + nn]);
          bl2[0] = __float_as_uint(vns_lo[(k0 + t) * SS + nn]);
          bl2[1] = __float_as_uint(vns_lo[(k0 + t + 4) * SS + nn]);
#pragma unroll
          for (int mi = 0; mi < 2; mi++) {
            mma_tf32(acc2[mi][ni], ah[mi], bh2);
            mma_tf32(acc2[mi][ni], ah[mi], bl2);
            mma_tf32(acc2[mi][ni], al[mi], bh2);
          }
        }
      }
      float gl = edcS[63];
#pragma unroll
      for (int mi = 0; mi < 2; mi++)
#pragma unroll
        for (int ni = 0; ni < 4; ni++)
#pragma unroll
          for (int r = 0; r < 4; r++) {
            int d = m0u + mi * 16 + g + ((r & 2) ? 8 : 0);
            int e = ni * 8 + 2 * t + (r & 1);
            float sNew = gl * S[d * SS + e] + acc2[mi][ni][r];
            S[d * SS + e] = sNew;
            uint32_t hh, ll;
            split2(sNew, hh, ll);
            S_hi[d * SS + e] = __uint_as_float(hh);
            S_lo[d * SS + e] = __uint_as_float(ll);
          }
    }
    __syncthreads();
  }
}

// ---------------------------------------------------------------------------
extern "C" void kernel_launch(void* const* d_in, const int* in_sizes, int n_in,
                              void* d_out, int out_size) {
  (void)in_sizes; (void)n_in; (void)out_size;
  const float* x    = (const float*)d_in[0];
  const float* Ww   = (const float*)d_in[1];
  const float* Wg   = (const float*)d_in[2];
  const float* Wo   = (const float*)d_in[3];
  const float* Wb   = (const float*)d_in[4];
  const float* Wa   = (const float*)d_in[5];
  const float* dtb  = (const float*)d_in[6];
  const float* Alog = (const float*)d_in[7];
  float* out = (float*)d_out;

  cudaFuncSetAttribute(k_mma, cudaFuncAttributeMaxDynamicSharedMemorySize, GM_SMEM);
  cudaFuncSetAttribute(k_chunk, cudaFuncAttributeMaxDynamicSharedMemorySize, K4_SMEM);
  cudaFuncSetAttribute(k_recur, cudaFuncAttributeMaxDynamicSharedMemorySize, K5_SMEM);

  k_proj_small<<<BTn, 256>>>(x, Wg, Wb, Wa, dtb, Alog);
  k_cumsum<<<BHn * Nchunk, 64>>>();
  k_mma<<<dim3(Dn/128, BTn/128), 256, GM_SMEM>>>(x, Ww, x, nullptr, 0);
  k_chunk<<<BHn * Nchunk, 256, K4_SMEM>>>();
  k_recur<<<BHn * 4, 256, K5_SMEM>>>();
  k_mma<<<dim3(Dn/128, BTn/128), 256, GM_SMEM>>>(nullptr, Wo, x, out, 1);
}

// round 14
// speedup vs baseline: 1.4649x; 1.0545x over previous
#include <cuda_runtime.h>
#include <math.h>
#include <stdint.h>

#define Bn 4
#define Tn 8192
#define Dn 1024
#define Hn 8
#define HDn 128
#define Cn 64
#define Nchunk 128
#define BTn (Bn*Tn)
#define BHn (Bn*Hn)

// ---------------- scratch (device globals; no cudaMalloc allowed) ----------
__device__ float g_v[(size_t)BTn*Dn];       // v*beta -> v' (in place)
__device__ float g_rk[(size_t)BTn*Dn];      // normalized read keys, (B,H,T,d)
__device__ float g_wkcd[(size_t)BTn*Dn];    // wk_cumdecay, (B,H,T,d)
__device__ float g_o[(size_t)BTn*Dn];       // gated per-head output, (B,T,D)
__device__ float g_attn[(size_t)BHn*Nchunk*Cn*Cn];
__device__ float g_beta[BHn*Tn];            // (B,H,T)
__device__ float g_gate[BHn*Tn];
__device__ float g_dec[BHn*Tn];             // decay, then in-chunk cumsum (in place)

__device__ __forceinline__ float warp_sum(float v) {
#pragma unroll
  for (int o = 16; o > 0; o >>= 1) v += __shfl_xor_sync(0xffffffffu, v, o);
  return v;
}

// ======================= mma.sync helpers ===================================
__device__ __forceinline__ uint32_t smem_u32(const void* p) {
  uint32_t a;
  asm("{ .reg .u64 t; cvta.to.shared.u64 t, %1; cvt.u32.u64 %0, t; }"
      : "=r"(a) : "l"(p));
  return a;
}

__device__ __forceinline__ uint32_t tf32u(float a) {
  uint32_t r; asm("cvt.rna.tf32.f32 %0, %1;" : "=r"(r) : "f"(a)); return r;
}

__device__ __forceinline__ void split2(float x, uint32_t& hi, uint32_t& lo) {
  hi = tf32u(x);
  lo = tf32u(x - __uint_as_float(hi));
}

__device__ __forceinline__ void mma_tf32(float* c, const uint32_t* a,
                                         const uint32_t* b) {
  asm volatile(
      "mma.sync.aligned.m16n8k8.row.col.f32.tf32.tf32.f32 "
      "{%0,%1,%2,%3}, {%4,%5,%6,%7}, {%8,%9}, {%0,%1,%2,%3};"
      : "+f"(c[0]), "+f"(c[1]), "+f"(c[2]), "+f"(c[3])
      : "r"(a[0]), "r"(a[1]), "r"(a[2]), "r"(a[3]), "r"(b[0]), "r"(b[1]));
}

__device__ __forceinline__ void mma_bf16(float* c, const uint32_t* a,
                                         const uint32_t* b) {
  asm volatile(
      "mma.sync.aligned.m16n8k16.row.col.f32.bf16.bf16.f32 "
      "{%0,%1,%2,%3}, {%4,%5,%6,%7}, {%8,%9}, {%0,%1,%2,%3};"
      : "+f"(c[0]), "+f"(c[1]), "+f"(c[2]), "+f"(c[3])
      : "r"(a[0]), "r"(a[1]), "r"(a[2]), "r"(a[3]), "r"(b[0]), "r"(b[1]));
}

// pack (elem_k+1, elem_k) -> bf16x2 word (low half = elem_k)
__device__ __forceinline__ uint32_t bf16pack(float hi_elem, float lo_elem) {
  uint32_t r;
  asm("cvt.rn.bf16x2.f32 %0, %1, %2;" : "=r"(r) : "f"(hi_elem), "f"(lo_elem));
  return r;
}

// split a float pair into hi word + lo (residual) word
__device__ __forceinline__ void packsplit(float x0, float x1,
                                          uint32_t& wh, uint32_t& wl) {
  wh = bf16pack(x1, x0);
  float q0 = x0 - __uint_as_float(wh << 16);
  float q1 = x1 - __uint_as_float(wh & 0xffff0000u);
  wl = bf16pack(q1, q0);
}

__device__ __forceinline__ void cp16(uint32_t dst, const void* src) {
  asm volatile("cp.async.cg.shared.global [%0], [%1], 16;"
               :: "r"(dst), "l"(src) : "memory");
}
#define CP_COMMIT() asm volatile("cp.async.commit_group;" ::: "memory")
#define CP_WAIT0() asm volatile("cp.async.wait_group 0;" ::: "memory")

// ---------------- 1) per-token projections, 4 tokens per block -------------
__global__ __launch_bounds__(256) void k_proj_small(
    const float* __restrict__ x, const float* __restrict__ Wg,
    const float* __restrict__ Wb, const float* __restrict__ Wa,
    const float* __restrict__ dtb, const float* __restrict__ Alog) {
  __shared__ float xs[4*Dn];
  int row0 = blockIdx.x * 4;
  const float* xr = x + (size_t)row0 * Dn;
  for (int i = threadIdx.x; i < 4*Dn; i += 256) xs[i] = xr[i];
  __syncthreads();
  int h = threadIdx.x >> 5, lane = threadIdx.x & 31;
  const float* wg = Wg + h * Dn;
  const float* wb = Wb + h * Dn;
  const float* wa = Wa + h * Dn;
  float sg[4] = {0,0,0,0}, sb[4] = {0,0,0,0}, sa[4] = {0,0,0,0};
  for (int i = lane; i < Dn; i += 32) {
    float wgv = wg[i], wbv = wb[i], wav = wa[i];
#pragma unroll
    for (int tk = 0; tk < 4; tk++) {
      float xv = xs[tk*Dn + i];
      sg[tk] += xv * wgv; sb[tk] += xv * wbv; sa[tk] += xv * wav;
    }
  }
  float ss[4] = {0,0,0,0};
  for (int i = lane; i < HDn; i += 32) {
#pragma unroll
    for (int tk = 0; tk < 4; tk++) {
      float v = xs[tk*Dn + h*HDn + i]; ss[tk] += v*v;
    }
  }
#pragma unroll
  for (int tk = 0; tk < 4; tk++) {
    sg[tk] = warp_sum(sg[tk]); sb[tk] = warp_sum(sb[tk]);
    sa[tk] = warp_sum(sa[tk]); ss[tk] = warp_sum(ss[tk]);
  }
  float Ae = expf(Alog[h]);
  float dtv = dtb[h];
#pragma unroll
  for (int tk = 0; tk < 4; tk++) {
    int row = row0 + tk;
    float inv = 1.0f / fmaxf(sqrtf(ss[tk]), 1e-12f);
    int b = row >> 13, t = row & (Tn - 1);
    size_t bh = (size_t)b * Hn + h;
    float* rko = g_rk + (bh * Tn + t) * HDn;
    for (int i = lane; i < HDn; i += 32) rko[i] = xs[tk*Dn + h*HDn + i] * inv;
    if (lane == 0) {
      g_gate[bh*Tn + t] = 1.0f / (1.0f + expf(-sg[tk]));
      g_beta[bh*Tn + t] = 1.0f / (1.0f + expf(-sb[tk]));
      float z = sa[tk] + dtv;
      float sp = (z > 20.0f) ? z : log1pf(expf(z));
      g_dec[bh*Tn + t] = -Ae * sp;
    }
  }
}

// ---------------- 2) in-chunk cumsum of decay ------------------------------
__global__ void k_cumsum() {
  int idx = blockIdx.x;                  // bh*N + n
  int bh = idx >> 7, n = idx & (Nchunk - 1);
  size_t base = (size_t)bh * Tn + (size_t)n * Cn;
  float v = g_dec[base + threadIdx.x];
  int lane = threadIdx.x & 31, w = threadIdx.x >> 5;
#pragma unroll
  for (int o = 1; o < 32; o <<= 1) {
    float u = __shfl_up_sync(0xffffffffu, v, o);
    if (lane >= o) v += u;
  }
  __shared__ float tot;
  if (w == 0 && lane == 31) tot = v;
  __syncthreads();
  if (w == 1) v += tot;
  g_dec[base + threadIdx.x] = v;
}

// ---------------- 3/6) mma.sync bf16 GEMM, cp.async landing, 2 CTA/SM ------
#define KCH 32                            // fp32 K per chunk
#define LSTR 36                           // landing stride (f32)
#define LAND_F (2*128*LSTR)               // A+B landing = 9216 floats
#define BSTR 20                           // plane words/row (16 + 4 pad)
#define PLANE (128*BSTR)                  // 2560 words
#define GM_SMEM ((LAND_F + 4*PLANE)*4)    // 77,824 B -> 2 CTAs/SM

__global__ __launch_bounds__(256, 2) void k_mma(
    const float* __restrict__ Ain, const float* __restrict__ Bw,
    const float* __restrict__ X, float* __restrict__ Out, int mode) {
  extern __shared__ float sf[];
  float* land = sf;
  uint32_t* pl = (uint32_t*)(sf + LAND_F);
  uint32_t land_u = smem_u32(sf);
  int tid = threadIdx.x, wid = tid >> 5, lane = tid & 31;
  int n0 = blockIdx.x * 128;
  int m0 = blockIdx.y * 128;
  int wm = wid >> 2, wn = wid & 3;       // warp tile: rows wm*64, cols wn*32
  int g = lane >> 2, t = lane & 3;

  // device-side resolution of the device-global operand (ATS trap otherwise)
  const float* A = (mode == 0) ? Ain : (const float*)g_o;

  float acc[4][4][4];
#pragma unroll
  for (int mi = 0; mi < 4; mi++)
#pragma unroll
    for (int ni = 0; ni < 4; ni++)
#pragma unroll
      for (int r = 0; r < 4; r++) acc[mi][ni][r] = 0.0f;

  int lrow = tid >> 3, lc4 = tid & 7;

  auto cp_issue = [&](int kc) {
#pragma unroll
    for (int q = 0; q < 4; q++) {
      int row = lrow + 32 * q;
      cp16(land_u + (uint32_t)(row * LSTR + lc4 * 4) * 4,
           A + (size_t)(m0 + row) * Dn + kc * KCH + lc4 * 4);
      cp16(land_u + (uint32_t)((128 + row) * LSTR + lc4 * 4) * 4,
           Bw + (size_t)(n0 + row) * Dn + kc * KCH + lc4 * 4);
    }
    CP_COMMIT();
  };
  auto stage = [&]() {
#pragma unroll
    for (int q = 0; q < 4; q++) {
      int row = lrow + 32 * q;
      float4 va = *(const float4*)(land + row * LSTR + lc4 * 4);
      float4 vb = *(const float4*)(land + (128 + row) * LSTR + lc4 * 4);
      int off = row * BSTR + lc4 * 2;
      uint32_t h0, l0, h1, l1;
      packsplit(va.x, va.y, h0, l0);
      packsplit(va.z, va.w, h1, l1);
      *(uint2*)(pl + off) = make_uint2(h0, h1);
      *(uint2*)(pl + PLANE + off) = make_uint2(l0, l1);
      packsplit(vb.x, vb.y, h0, l0);
      packsplit(vb.z, vb.w, h1, l1);
      *(uint2*)(pl + 2*PLANE + off) = make_uint2(h0, h1);
      *(uint2*)(pl + 3*PLANE + off) = make_uint2(l0, l1);
    }
  };

  const int NC = Dn / KCH;               // 32 chunks
  cp_issue(0);
  CP_WAIT0();                            // own data landed (same-thread mapping)
  for (int kc = 0; kc < NC; kc++) {
    stage();
    __syncthreads();                     // planes visible; land fully read
    if (kc + 1 < NC) cp_issue(kc + 1);
    const uint32_t* Ahi = pl;
    const uint32_t* Alo = Ahi + PLANE;
    const uint32_t* Bhi = Alo + PLANE;
    const uint32_t* Blo = Bhi + PLANE;
#pragma unroll
    for (int kk = 0; kk < 2; kk++) {     // K=16 per step
      uint32_t ah[4][4], al[4][4];
#pragma unroll
      for (int mi = 0; mi < 4; mi++) {
        int r0 = wm * 64 + mi * 16 + g;
        int o0 = r0 * BSTR + kk * 8 + t;
        int o1 = (r0 + 8) * BSTR + kk * 8 + t;
        ah[mi][0] = Ahi[o0]; ah[mi][1] = Ahi[o1];
        ah[mi][2] = Ahi[o0 + 4]; ah[mi][3] = Ahi[o1 + 4];
        al[mi][0] = Alo[o0]; al[mi][1] = Alo[o1];
        al[mi][2] = Alo[o0 + 4]; al[mi][3] = Alo[o1 + 4];
      }
      uint32_t bh[4][2], bl[4][2];
#pragma unroll
      for (int ni = 0; ni < 4; ni++) {
        int r0 = wn * 32 + ni * 8 + g;
        int o0 = r0 * BSTR + kk * 8 + t;
        bh[ni][0] = Bhi[o0]; bh[ni][1] = Bhi[o0 + 4];
        bl[ni][0] = Blo[o0]; bl[ni][1] = Blo[o0 + 4];
      }
#pragma unroll
      for (int mi = 0; mi < 4; mi++)
#pragma unroll
        for (int ni = 0; ni < 4; ni++) {
          mma_bf16(acc[mi][ni], ah[mi], bh[ni]);
          mma_bf16(acc[mi][ni], ah[mi], bl[ni]);
          mma_bf16(acc[mi][ni], al[mi], bh[ni]);
        }
    }
    if (kc + 1 < NC) CP_WAIT0();         // own next-chunk data landed
    __syncthreads();                     // mma done before planes overwritten
  }

  int h = blockIdx.x;                     // mode 0: 128-wide n-block == head
#pragma unroll
  for (int mi = 0; mi < 4; mi++) {
#pragma unroll
    for (int rr = 0; rr < 2; rr++) {
      int m = m0 + wm * 64 + mi * 16 + g + rr * 8;
      if (mode == 0) {
        int b = m >> 13, tt = m & (Tn - 1);
        size_t bhT = ((size_t)(b * Hn + h)) * Tn + tt;
        float beta = g_beta[bhT];
        float* vout = g_v + bhT * HDn;
#pragma unroll
        for (int ni = 0; ni < 4; ni++) {
          int col = wn * 32 + ni * 8 + 2 * t;
          float2 val;
          val.x = acc[mi][ni][rr * 2 + 0] * beta;
          val.y = acc[mi][ni][rr * 2 + 1] * beta;
          *(float2*)(vout + col) = val;
        }
      } else {
#pragma unroll
        for (int ni = 0; ni < 4; ni++) {
          int ncol = n0 + wn * 32 + ni * 8 + 2 * t;
          size_t off = (size_t)m * Dn + ncol;
          float2 xv = *(const float2*)(X + off);
          float2 val;
          val.x = xv.x + acc[mi][ni][rr * 2 + 0];
          val.y = xv.y + acc[mi][ni][rr * 2 + 1];
          *(float2*)(Out + off) = val;
        }
      }
    }
  }
}

// ---------------- 4) per-chunk, all-bf16, register-resident inversion ------
#define KBS 68
#define TBS 136
#define K4_SMEM ((2*65*KBS + 64*65 + 4*64) * 4)
__global__ __launch_bounds__(256) void k_chunk() {
  extern __shared__ float smf[];
  uint32_t* kbh = (uint32_t*)smf;
  uint32_t* kbl = kbh + 65*KBS;
  uint32_t* tbh = kbh;                   // overlay (P-phase done before use)
  uint32_t* tbl = kbl;
  float* Asm   = smf + 2*65*KBS;         // 64 x 65
  float* decS  = Asm + 64*65;
  float* betaS = decS + 64;
  float* facS  = betaS + 64;
  float* beS   = facS + 64;

  int cid = blockIdx.x;                  // bh*N + n
  int bh = cid >> 7, n = cid & (Nchunk - 1);
  int tid = threadIdx.x;
  int wid = tid >> 5, lane = tid & 31;
  int g = lane >> 2, t = lane & 3;
  size_t tbase = (size_t)bh * Tn + (size_t)n * Cn;
  const float* rkG = g_rk + tbase * HDn;

  if (tid < 64) {
    float dv = g_dec[tbase + tid];
    float bv = g_beta[tbase + tid];
    decS[tid] = dv; betaS[tid] = bv; beS[tid] = bv * __expf(dv);
  }
  // kb planes rows 1..64 = rk rows 0..63
  for (int i = tid; i < 64*64; i += 256) {
    int r1 = i >> 6, w = i & 63;
    float2 v2 = *(const float2*)(rkG + (size_t)r1 * HDn + 2*w);
    uint32_t wh, wl;
    packsplit(v2.x, v2.y, wh, wl);
    kbh[(r1+1)*KBS + w] = wh;
    kbl[(r1+1)*KBS + w] = wl;
  }
  if (tid < 64) {
    float2 v2 = (n == 0) ? make_float2(0.f, 0.f)
                         : *(const float2*)(g_rk + (tbase - 1) * HDn + 2*tid);
    uint32_t wh, wl;
    packsplit(v2.x, v2.y, wh, wl);
    kbh[tid] = wh; kbl[tid] = wl;
  }
  __syncthreads();
  if (tid < 64) facS[tid] = (tid == 0) ? 0.0f
                          : betaS[tid] * __expf(decS[tid] - decS[tid-1]);

  // ---- P[i][j] = rk_i . wk_j via bf16 mma (K=128 -> 8 k16 blocks) ---------
  int wr = wid >> 2, wc = wid & 3;       // 2 x 4 warp grid over 64x64
  float pacc[2][2][4];
#pragma unroll
  for (int mi = 0; mi < 2; mi++)
#pragma unroll
    for (int ni = 0; ni < 2; ni++)
#pragma unroll
      for (int r = 0; r < 4; r++) pacc[mi][ni][r] = 0.0f;

#pragma unroll 1
  for (int ks = 0; ks < 8; ks++) {
    int w1 = ks*8 + t;
    uint32_t ah[2][4], al[2][4];
#pragma unroll
    for (int mi = 0; mi < 2; mi++) {
      int r0 = 1 + wr*32 + mi*16 + g;
      ah[mi][0] = kbh[r0*KBS + w1];     ah[mi][1] = kbh[(r0+8)*KBS + w1];
      ah[mi][2] = kbh[r0*KBS + w1 + 4]; ah[mi][3] = kbh[(r0+8)*KBS + w1 + 4];
      al[mi][0] = kbl[r0*KBS + w1];     al[mi][1] = kbl[(r0+8)*KBS + w1];
      al[mi][2] = kbl[r0*KBS + w1 + 4]; al[mi][3] = kbl[(r0+8)*KBS + w1 + 4];
    }
    uint32_t bhf[2][2], blf[2][2];
#pragma unroll
    for (int ni = 0; ni < 2; ni++) {
      int nr = wc*16 + ni*8 + g;
      bhf[ni][0] = kbh[nr*KBS + w1]; bhf[ni][1] = kbh[nr*KBS + w1 + 4];
      blf[ni][0] = kbl[nr*KBS + w1]; blf[ni][1] = kbl[nr*KBS + w1 + 4];
    }
#pragma unroll
    for (int mi = 0; mi < 2; mi++)
#pragma unroll
      for (int ni = 0; ni < 2; ni++) {
        mma_bf16(pacc[mi][ni], ah[mi], bhf[ni]);
        mma_bf16(pacc[mi][ni], ah[mi], blf[ni]);
        mma_bf16(pacc[mi][ni], al[mi], bhf[ni]);
      }
  }

  // epilogue: attn = P * exp(dec_i - dec_j) masked; P' lower into Asm
  float* attnOut = g_attn + (size_t)cid * 4096;
#pragma unroll
  for (int mi = 0; mi < 2; mi++)
#pragma unroll
    for (int ni = 0; ni < 2; ni++)
#pragma unroll
      for (int r = 0; r < 4; r++) {
        int i = wr*32 + mi*16 + g + ((r & 2) ? 8 : 0);
        int j = wc*16 + ni*8 + 2*t + (r & 1);
        float aval = 0.0f;
        if (i >= j) {
          aval = pacc[mi][ni][r] * __expf(decS[i] - decS[j]);
          Asm[i*65 + j] = aval;
        }
        attnOut[i*64 + j] = aval;
      }
  __syncthreads();

  // M^T into Asm upper: slot(row j, col i) = M[i][j] = P'[i-1][j]*fac[i]
  for (int idx = tid; idx < 4096; idx += 256) {
    int i = idx >> 6, j = idx & 63;
    if (i > j) Asm[j*65 + i] = Asm[(i-1)*65 + j] * facS[i];
  }
  __syncthreads();

  // ---- register-resident forward substitution: X = (I+M)^-1 --------------
  // warp w owns cols [8w, 8w+8); lane owns rows 2*lane, 2*lane+1
  {
    int c0 = wid * 8;
    int r0 = 2 * lane, r1 = r0 + 1;
    float X0[8], X1[8];
#pragma unroll
    for (int k = 0; k < 8; k++) {
      X0[k] = (r0 == c0 + k) ? 1.0f : 0.0f;
      X1[k] = (r1 == c0 + k) ? 1.0f : 0.0f;
    }
    for (int i = 0; i < 63; i++) {
      float xi[8];
      int src = i >> 1;
      if (i & 1) {
#pragma unroll
        for (int k = 0; k < 8; k++) xi[k] = __shfl_sync(0xffffffffu, X1[k], src);
      } else {
#pragma unroll
        for (int k = 0; k < 8; k++) xi[k] = __shfl_sync(0xffffffffu, X0[k], src);
      }
      if (r0 > i) {
        float m = Asm[i*65 + r0];
#pragma unroll
        for (int k = 0; k < 8; k++) X0[k] -= m * xi[k];
      }
      if (r1 > i) {
        float m = Asm[i*65 + r1];
#pragma unroll
        for (int k = 0; k < 8; k++) X1[k] -= m * xi[k];
      }
    }
    __syncthreads();                     // all M^T reads done before overwrite
#pragma unroll
    for (int k = 0; k < 8; k++) {
      Asm[r0*65 + c0 + k] = X0[k];
      Asm[r1*65 + c0 + k] = X1[k];
    }
  }

  // stage tb planes with scaled wk (transposed)
  for (int i = tid; i < 32*128; i += 256) {
    int w = i >> 7, d = i & 127;
    int j0 = 2*w;
    float x0 = (j0 == 0)
        ? ((n == 0) ? 0.0f : g_rk[(tbase - 1) * HDn + d])
        : rkG[(size_t)(j0 - 1) * HDn + d];
    float x1 = rkG[(size_t)j0 * HDn + d];
    x0 *= beS[j0]; x1 *= beS[j0 + 1];
    uint32_t wh, wl;
    packsplit(x0, x1, wh, wl);
    tbh[w*TBS + d] = wh; tbl[w*TBS + d] = wl;
  }
  __syncthreads();

  // C = Asm @ X (64x128, K=64 -> 4 k16 blocks); A split on the fly
  int wr2 = wid >> 1, wc2 = wid & 1;
  auto triMulBf = [&](float* outp) {
    float cacc[8][4];
#pragma unroll
    for (int ni = 0; ni < 8; ni++)
#pragma unroll
      for (int r = 0; r < 4; r++) cacc[ni][r] = 0.0f;
#pragma unroll 1
    for (int ks = 0; ks < 4; ks++) {
      int w1 = ks*8 + t;
      int r0 = wr2*16 + g;
      uint32_t ah4[4], al4[4];
      packsplit(Asm[r0*65 + 2*w1],       Asm[r0*65 + 2*w1 + 1],     ah4[0], al4[0]);
      packsplit(Asm[(r0+8)*65 + 2*w1],   Asm[(r0+8)*65 + 2*w1 + 1], ah4[1], al4[1]);
      packsplit(Asm[r0*65 + 2*w1 + 8],   Asm[r0*65 + 2*w1 + 9],     ah4[2], al4[2]);
      packsplit(Asm[(r0+8)*65 + 2*w1+8], Asm[(r0+8)*65 + 2*w1 + 9], ah4[3], al4[3]);
#pragma unroll
      for (int ni = 0; ni < 8; ni++) {
        int nn = wc2*64 + ni*8 + g;
        uint32_t b2h[2], b2l[2];
        b2h[0] = tbh[w1*TBS + nn]; b2h[1] = tbh[(w1+4)*TBS + nn];
        b2l[0] = tbl[w1*TBS + nn]; b2l[1] = tbl[(w1+4)*TBS + nn];
        mma_bf16(cacc[ni], ah4, b2h);
        mma_bf16(cacc[ni], ah4, b2l);
        mma_bf16(cacc[ni], al4, b2h);
      }
    }
#pragma unroll
    for (int ni = 0; ni < 8; ni++)
#pragma unroll
      for (int rr = 0; rr < 2; rr++) {
        int c = wr2*16 + g + rr*8;
        int d = wc2*64 + ni*8 + 2*t;
        float2 val;
        val.x = cacc[ni][rr*2 + 0];
        val.y = cacc[ni][rr*2 + 1];
        *(float2*)(outp + (size_t)c*HDn + d) = val;
      }
  };

  // wkcd = A^-1 @ (wk * beta * exp(dec))
  triMulBf(g_wkcd + tbase * HDn);
  __syncthreads();

  // tb <- v (already *beta)
  {
    const float* vG = g_v + tbase * HDn;
    for (int i = tid; i < 32*128; i += 256) {
      int w = i >> 7, d = i & 127;
      float x0 = vG[(size_t)(2*w) * HDn + d];
      float x1 = vG[(size_t)(2*w + 1) * HDn + d];
      uint32_t wh, wl;
      packsplit(x0, x1, wh, wl);
      tbh[w*TBS + d] = wh; tbl[w*TBS + d] = wl;
    }
  }
  __syncthreads();

  // v' = A^-1 @ v
  triMulBf(g_v + tbase * HDn);
}

// ---------------- 5) inter-chunk recurrence, tensorized (tf32) -------------
#define RS 132
#define SS 40
#define ATS 68
#define K5_SMEM ((3*128*SS + 4*64*SS + 64*ATS + 64*RS + 65*RS + 2*64) * 4)
__global__ __launch_bounds__(256) void k_recur() {
  extern __shared__ float smf[];
  float* S      = smf;                   // 128 x 40 fp32
  float* S_hi   = S     + 128*SS;
  float* S_lo   = S_hi  + 128*SS;
  float* vn_hi  = S_lo  + 128*SS;
  float* vn_lo  = vn_hi + 64*SS;
  float* vns_hi = vn_lo + 64*SS;
  float* vns_lo = vns_hi+ 64*SS;
  float* attnS  = vns_lo+ 64*SS;         // 64 x 68
  float* bufA   = attnS + 64*ATS;        // 64 x 132 (wkcd)
  float* bufB   = bufA  + 64*RS;         // 65 x 132 (row0=wk0, 1..64=rk)
  float* edwS   = bufB  + 65*RS;
  float* edcS   = edwS  + 64;

  uint32_t smb = smem_u32(smf);
  int blk = blockIdx.x;                  // bh*4 + eg
  int bh = blk >> 2, eg = blk & 3;
  int e0 = eg * 32;
  int b = bh >> 3, h = bh & 7;
  int tid = threadIdx.x;
  int wid = tid >> 5, lane = tid & 31;
  int g = lane >> 2, t = lane & 3;

  for (int i = tid; i < 3*128*SS; i += 256) S[i] = 0.0f;
  __syncthreads();

  uint32_t sm_attn = smb + (uint32_t)((attnS - smf) * 4);
  uint32_t sm_bufA = smb + (uint32_t)((bufA - smf) * 4);
  uint32_t sm_bufB = smb + (uint32_t)((bufB - smf) * 4);

  for (int n = 0; n < Nchunk; n++) {
    size_t tbase = (size_t)bh * Tn + (size_t)n * Cn;
    {
      const float* aG = g_attn + ((size_t)bh * Nchunk + n) * 4096;
#pragma unroll
      for (int q = 0; q < 4; q++) {
        int idx = q * 256 + tid;
        int r = idx >> 4, c4 = idx & 15;
        cp16(sm_attn + (uint32_t)(r * ATS + c4 * 4) * 4, aG + r * 64 + c4 * 4);
      }
      const float* wkcdG = g_wkcd + tbase * HDn;
      const float* rkG = g_rk + tbase * HDn;
#pragma unroll
      for (int q = 0; q < 8; q++) {
        int idx = q * 256 + tid;
        int r = idx >> 5, c4 = idx & 31;
        cp16(sm_bufA + (uint32_t)(r * RS + c4 * 4) * 4,
             wkcdG + (size_t)r * HDn + c4 * 4);
        cp16(sm_bufB + (uint32_t)((r + 1) * RS + c4 * 4) * 4,
             rkG + (size_t)r * HDn + c4 * 4);
      }
      if (tid < 32) {
        if (n == 0) {
          float4 z = make_float4(0.f, 0.f, 0.f, 0.f);
          *(float4*)(bufB + tid * 4) = z;
        } else {
          cp16(sm_bufB + (uint32_t)(tid * 4) * 4,
               g_rk + (tbase - 1) * HDn + tid * 4);
        }
      }
      if (tid < 64) {
        float dv = g_dec[tbase + tid];
        float d63 = g_dec[tbase + 63];
        edcS[tid] = __expf(dv);
        edwS[tid] = __expf(d63 - dv);
      }
      CP_COMMIT(); CP_WAIT0();
    }
    __syncthreads();

    float acc[4][4];
    int w4 = wid & 3;
    int m0 = w4 * 16;
    bool isV = (wid < 4);
    if (isV) {
      const float* vG = g_v + tbase * HDn;
#pragma unroll
      for (int ni = 0; ni < 4; ni++) {
        int e = ni * 8 + 2 * t;
        float2 p0 = *(const float2*)(vG + (size_t)(m0 + g) * HDn + e0 + e);
        float2 p1 = *(const float2*)(vG + (size_t)(m0 + 8 + g) * HDn + e0 + e);
        acc[ni][0] = p0.x; acc[ni][1] = p0.y;
        acc[ni][2] = p1.x; acc[ni][3] = p1.y;
      }
    } else {
#pragma unroll
      for (int ni = 0; ni < 4; ni++)
#pragma unroll
        for (int r = 0; r < 4; r++) acc[ni][r] = 0.0f;
    }
    {
      const float* Abuf = isV ? bufA : (bufB + RS);
      float sgn = isV ? -1.0f : 1.0f;
#pragma unroll 2
      for (int ks = 0; ks < 16; ks++) {
        int k0 = ks * 8;
        uint32_t ah[4], al[4];
        split2(sgn * Abuf[(m0 + g) * RS + k0 + t],         ah[0], al[0]);
        split2(sgn * Abuf[(m0 + 8 + g) * RS + k0 + t],     ah[1], al[1]);
        split2(sgn * Abuf[(m0 + g) * RS + k0 + t + 4],     ah[2], al[2]);
        split2(sgn * Abuf[(m0 + 8 + g) * RS + k0 + t + 4], ah[3], al[3]);
#pragma unroll
        for (int ni = 0; ni < 4; ni++) {
          int nn = ni * 8 + g;
          uint32_t bh2[2], bl2[2];
          bh2[0] = __float_as_uint(S_hi[(k0 + t) * SS + nn]);
          bh2[1] = __float_as_uint(S_hi[(k0 + t + 4) * SS + nn]);
          bl2[0] = __float_as_uint(S_lo[(k0 + t) * SS + nn]);
          bl2[1] = __float_as_uint(S_lo[(k0 + t + 4) * SS + nn]);
          mma_tf32(acc[ni], ah, bh2);
          mma_tf32(acc[ni], ah, bl2);
          mma_tf32(acc[ni], al, bh2);
        }
      }
    }
    if (isV) {
#pragma unroll
      for (int ni = 0; ni < 4; ni++)
#pragma unroll
        for (int r = 0; r < 4; r++) {
          int c = m0 + g + ((r & 2) ? 8 : 0);
          int e = ni * 8 + 2 * t + (r & 1);
          float v = acc[ni][r];
          uint32_t hh, ll;
          split2(v, hh, ll);
          vn_hi[c * SS + e] = __uint_as_float(hh);
          vn_lo[c * SS + e] = __uint_as_float(ll);
          float vs = v * edwS[c];
          split2(vs, hh, ll);
          vns_hi[c * SS + e] = __uint_as_float(hh);
          vns_lo[c * SS + e] = __uint_as_float(ll);
        }
    } else {
#pragma unroll
      for (int ni = 0; ni < 4; ni++) {
        acc[ni][0] *= edcS[m0 + g];     acc[ni][1] *= edcS[m0 + g];
        acc[ni][2] *= edcS[m0 + 8 + g]; acc[ni][3] *= edcS[m0 + 8 + g];
      }
    }
    __syncthreads();

    if (!isV) {
#pragma unroll 1
      for (int ks = 0; ks < 8; ks++) {
        int k0 = ks * 8;
        uint32_t ah[4], al[4];
        split2(attnS[(m0 + g) * ATS + k0 + t],         ah[0], al[0]);
        split2(attnS[(m0 + 8 + g) * ATS + k0 + t],     ah[1], al[1]);
        split2(attnS[(m0 + g) * ATS + k0 + t + 4],     ah[2], al[2]);
        split2(attnS[(m0 + 8 + g) * ATS + k0 + t + 4], ah[3], al[3]);
#pragma unroll
        for (int ni = 0; ni < 4; ni++) {
          int nn = ni * 8 + g;
          uint32_t bh2[2], bl2[2];
          bh2[0] = __float_as_uint(vn_hi[(k0 + t) * SS + nn]);
          bh2[1] = __float_as_uint(vn_hi[(k0 + t + 4) * SS + nn]);
          bl2[0] = __float_as_uint(vn_lo[(k0 + t) * SS + nn]);
          bl2[1] = __float_as_uint(vn_lo[(k0 + t + 4) * SS + nn]);
          mma_tf32(acc[ni], ah, bh2);
          mma_tf32(acc[ni], ah, bl2);
          mma_tf32(acc[ni], al, bh2);
        }
      }
#pragma unroll
      for (int rr = 0; rr < 2; rr++) {
        int c = m0 + g + rr * 8;
        int tg = n * Cn + c;
        float gate = g_gate[(size_t)bh * Tn + tg];
        float* op = g_o + ((size_t)b * Tn + tg) * Dn + h * HDn + e0;
#pragma unroll
        for (int ni = 0; ni < 4; ni++) {
          float2 val;
          val.x = acc[ni][rr * 2 + 0] * gate;
          val.y = acc[ni][rr * 2 + 1] * gate;
          *(float2*)(op + ni * 8 + 2 * t) = val;
        }
      }
    } else {
      int m0u = w4 * 32;
      float acc2[2][4][4];
#pragma unroll
      for (int mi = 0; mi < 2; mi++)
#pragma unroll
        for (int ni = 0; ni < 4; ni++)
#pragma unroll
          for (int r = 0; r < 4; r++) acc2[mi][ni][r] = 0.0f;
#pragma unroll 1
      for (int ks = 0; ks < 8; ks++) {
        int k0 = ks * 8;
        uint32_t ah[2][4], al[2][4];
#pragma unroll
        for (int mi = 0; mi < 2; mi++) {
          int mm = m0u + mi * 16 + g;
          split2(bufB[(k0 + t) * RS + mm],         ah[mi][0], al[mi][0]);
          split2(bufB[(k0 + t) * RS + mm + 8],     ah[mi][1], al[mi][1]);
          split2(bufB[(k0 + t + 4) * RS + mm],     ah[mi][2], al[mi][2]);
          split2(bufB[(k0 + t + 4) * RS + mm + 8], ah[mi][3], al[mi][3]);
        }
#pragma unroll
        for (int ni = 0; ni < 4; ni++) {
          int nn = ni * 8 + g;
          uint32_t bh2[2], bl2[2];
          bh2[0] = __float_as_uint(vns_hi[(k0 + t) * SS + nn]);
          bh2[1] = __float_as_uint(vns_hi[(k0 + t + 4) * SS + nn]);
          bl2[0] = __float_as_uint(vns_lo[(k0 + t) * SS + nn]);
          bl2[1] = __float_as_uint(vns_lo[(k0 + t + 4) * SS + nn]);
#pragma unroll
          for (int mi = 0; mi < 2; mi++) {
            mma_tf32(acc2[mi][ni], ah[mi], bh2);
            mma_tf32(acc2[mi][ni], ah[mi], bl2);
            mma_tf32(acc2[mi][ni], al[mi], bh2);
          }
        }
      }
      float gl = edcS[63];
#pragma unroll
      for (int mi = 0; mi < 2; mi++)
#pragma unroll
        for (int ni = 0; ni < 4; ni++)
#pragma unroll
          for (int r = 0; r < 4; r++) {
            int d = m0u + mi * 16 + g + ((r & 2) ? 8 : 0);
            int e = ni * 8 + 2 * t + (r & 1);
            float sNew = gl * S[d * SS + e] + acc2[mi][ni][r];
            S[d * SS + e] = sNew;
            uint32_t hh, ll;
            split2(sNew, hh, ll);
            S_hi[d * SS + e] = __uint_as_float(hh);
            S_lo[d * SS + e] = __uint_as_float(ll);
          }
    }
    __syncthreads();
  }
}

// ---------------------------------------------------------------------------
extern "C" void kernel_launch(void* const* d_in, const int* in_sizes, int n_in,
                              void* d_out, int out_size) {
  (void)in_sizes; (void)n_in; (void)out_size;
  const float* x    = (const float*)d_in[0];
  const float* Ww   = (const float*)d_in[1];
  const float* Wg   = (const float*)d_in[2];
  const float* Wo   = (const float*)d_in[3];
  const float* Wb   = (const float*)d_in[4];
  const float* Wa   = (const float*)d_in[5];
  const float* dtb  = (const float*)d_in[6];
  const float* Alog = (const float*)d_in[7];
  float* out = (float*)d_out;

  cudaFuncSetAttribute(k_mma, cudaFuncAttributeMaxDynamicSharedMemorySize, GM_SMEM);
  cudaFuncSetAttribute(k_chunk, cudaFuncAttributeMaxDynamicSharedMemorySize, K4_SMEM);
  cudaFuncSetAttribute(k_recur, cudaFuncAttributeMaxDynamicSharedMemorySize, K5_SMEM);

  k_proj_small<<<BTn/4, 256>>>(x, Wg, Wb, Wa, dtb, Alog);
  k_cumsum<<<BHn * Nchunk, 64>>>();
  k_mma<<<dim3(Dn/128, BTn/128), 256, GM_SMEM>>>(x, Ww, x, nullptr, 0);
  k_chunk<<<BHn * Nchunk, 256, K4_SMEM>>>();
  k_recur<<<BHn * 4, 256, K5_SMEM>>>();
  k_mma<<<dim3(Dn/128, BTn/128), 256, GM_SMEM>>>(nullptr, Wo, x, out, 1);
}